// round 13
// baseline (speedup 1.0000x reference)
#include <cuda_runtime.h>
#include <cuda_bf16.h>
#include <math.h>

#define BATCH 2
#define CIN   64
#define COUT  128
#define HH    128
#define WW    128
#define HWSZ  (HH*WW)          // 16384
#define K1    576              // 9*64
#define K2C   1152             // 9*128
#define K2    1216             // + 64 identity rows

// ---------------- scratch (static device globals) ----------------------------
__device__ float g_off[BATCH * 18 * HWSZ];
__device__ float g_offp[8 * BATCH * 18 * HWSZ];             // per-chunk partials
__device__ float g_xt [BATCH * HWSZ * CIN];                 // x in HWC
__device__ float g_h1 [BATCH * HWSZ * COUT];                // h1 in HWC
__device__ __nv_bfloat16 g_w1h[COUT * K1], g_w1l[COUT * K1];
__device__ __nv_bfloat16 g_w2h[COUT * K2], g_w2l[COUT * K2];
__device__ float g_b1[COUT], g_b2[COUT];

// ---------------- PTX helpers (sm_80-era only; compute_103-safe) -------------
__device__ __forceinline__ unsigned smem_u32(const void* p) {
    unsigned a;
    asm("{ .reg .u64 t; cvta.to.shared.u64 t, %1; cvt.u32.u64 %0, t; }"
        : "=r"(a) : "l"(p));
    return a;
}
__device__ __forceinline__ void cp16(unsigned dst, const void* src) {
    asm volatile("cp.async.cg.shared.global [%0], [%1], 16;"
                 :: "r"(dst), "l"(src) : "memory");
}
__device__ __forceinline__ void cp_commit() {
    asm volatile("cp.async.commit_group;" ::: "memory");
}
__device__ __forceinline__ void cp_wait0() {
    asm volatile("cp.async.wait_group 0;" ::: "memory");
}
__device__ __forceinline__ void ldm_x4(unsigned a, unsigned r[4]) {
    asm volatile("ldmatrix.sync.aligned.m8n8.x4.shared.b16 {%0,%1,%2,%3}, [%4];"
                 : "=r"(r[0]), "=r"(r[1]), "=r"(r[2]), "=r"(r[3]) : "r"(a));
}
__device__ __forceinline__ void mma16816(float d[4], const unsigned a[4],
                                         unsigned b0, unsigned b1) {
    asm volatile(
        "mma.sync.aligned.m16n8k16.row.col.f32.bf16.bf16.f32 "
        "{%0,%1,%2,%3}, {%4,%5,%6,%7}, {%8,%9}, {%0,%1,%2,%3};"
        : "+f"(d[0]), "+f"(d[1]), "+f"(d[2]), "+f"(d[3])
        : "r"(a[0]), "r"(a[1]), "r"(a[2]), "r"(a[3]), "r"(b0), "r"(b1));
}
__device__ __forceinline__ unsigned pack_bf2(float a, float b) {
    return (unsigned)__bfloat16_as_ushort(__float2bfloat16(a)) |
           ((unsigned)__bfloat16_as_ushort(__float2bfloat16(b)) << 16);
}
__device__ __forceinline__ float lo_of(float v) {
    return v - __bfloat162float(__float2bfloat16(v));
}

// ---------------- merged prep (weights/bias) + x transpose -------------------
__device__ __forceinline__ float bn_scale(const float* g, const float* v, int o) {
    return g[o] * rsqrtf(v[o] + 1e-5f);
}
__device__ __forceinline__ void split_store(__nv_bfloat16* hd, __nv_bfloat16* ld,
                                            long i, float v) {
    __nv_bfloat16 h = __float2bfloat16(v);
    hd[i] = h;
    ld[i] = __float2bfloat16(v - __bfloat162float(h));
}

#define PREP_BLOCKS 896           // covers 229376 weight elements
#define XT_BLOCKS   8192          // covers 2M transpose elements

__global__ void prep_all(const float* __restrict__ x,
                         const float* __restrict__ dc1_w,
                         const float* __restrict__ dc2_w,
                         const float* __restrict__ id_w,
                         const float* __restrict__ id_b,
                         const float* __restrict__ bn1_g, const float* __restrict__ bn1_b,
                         const float* __restrict__ bn1_m, const float* __restrict__ bn1_v,
                         const float* __restrict__ bn2_g, const float* __restrict__ bn2_b,
                         const float* __restrict__ bn2_m, const float* __restrict__ bn2_v,
                         const float* __restrict__ bn3_g, const float* __restrict__ bn3_b,
                         const float* __restrict__ bn3_m, const float* __restrict__ bn3_v)
{
    if (blockIdx.x >= PREP_BLOCKS) {
        // transpose x CHW -> HWC
        long idx = (long)(blockIdx.x - PREP_BLOCKS) * blockDim.x + threadIdx.x;
        const long total = (long)BATCH * HWSZ * CIN;
        if (idx < total) {
            int c = (int)(idx & 63);
            long p = idx >> 6;
            int pix = (int)(p & (HWSZ - 1));
            int b = (int)(p >> 14);
            g_xt[idx] = x[((long)b * CIN + c) * HWSZ + pix];
        }
        return;
    }
    int idx = blockIdx.x * blockDim.x + threadIdx.x;
    if (idx < COUT) {
        int o = idx;
        float s1 = bn_scale(bn1_g, bn1_v, o);
        float s2 = bn_scale(bn2_g, bn2_v, o);
        float s3 = bn_scale(bn3_g, bn3_v, o);
        g_b1[o] = bn1_b[o] - bn1_m[o] * s1;
        g_b2[o] = (bn2_b[o] - bn2_m[o] * s2) + id_b[o] * s3 + (bn3_b[o] - bn3_m[o] * s3);
    }
    const int n1 = COUT * K1, n2 = COUT * K2C, n3 = COUT * CIN;
    if (idx < n1) {
        int o = idx / K1, kk = idx % K1;
        int c = kk / 9, n = kk % 9;
        float v = dc1_w[idx] * bn_scale(bn1_g, bn1_v, o);
        split_store(g_w1h, g_w1l, (long)o * K1 + n * CIN + c, v);
    } else if (idx < n1 + n2) {
        int r = idx - n1;
        int o = r / K2C, kk = r % K2C;
        int c = kk / 9, n = kk % 9;
        float v = dc2_w[r] * bn_scale(bn2_g, bn2_v, o);
        split_store(g_w2h, g_w2l, (long)o * K2 + n * COUT + c, v);
    } else if (idx < n1 + n2 + n3) {
        int r = idx - n1 - n2;
        int o = r / CIN, c = r % CIN;
        float v = id_w[r] * bn_scale(bn3_g, bn3_v, o);
        split_store(g_w2h, g_w2l, (long)o * K2 + K2C + c, v);
    }
}

// ---------------- offset conv: smem-tiled partial conv -----------------------
// use_h1==1 reads g_h1 (HWC); use_h1==0 reads x (CHW)
__global__ __launch_bounds__(128)
void offset_partial_kernel(const float* __restrict__ xext, int use_h1,
                           const float* __restrict__ ow, int C)
{
    __shared__ float xs[16][324];
    __shared__ float ws[16 * 9 * 18];
    const int CH = C / 16;
    const int z = blockIdx.z;
    const int b = z / CH, ch = z % CH, c0 = ch * 16;
    const int tx0 = blockIdx.x * 16, ty0 = blockIdx.y * 16;
    const int t = threadIdx.x;
    const int py = t >> 4, px = t & 15;

    for (int i = t; i < 16 * 162; i += 128) {
        int c = i / 162, r = i % 162, tap = r / 18, o = r % 18;
        ws[i] = ow[o * C * 9 + (c0 + c) * 9 + tap];
    }
    if (use_h1) {
        for (int i = t; i < 16 * 324; i += 128) {
            int c = i & 15, sp = i >> 4;
            int rr = sp / 18, cc = sp % 18;
            int gy = ty0 - 1 + rr, gx = tx0 - 1 + cc;
            float v = 0.f;
            if ((unsigned)gy < (unsigned)HH && (unsigned)gx < (unsigned)WW)
                v = g_h1[((long)b * HWSZ + gy * WW + gx) * COUT + c0 + c];
            xs[c][sp] = v;
        }
    } else {
        for (int i = t; i < 16 * 324; i += 128) {
            int c = i / 324, rr = (i % 324) / 18, cc = i % 18;
            int gy = ty0 - 1 + rr, gx = tx0 - 1 + cc;
            float v = 0.f;
            if ((unsigned)gy < (unsigned)HH && (unsigned)gx < (unsigned)WW)
                v = xext[((long)b * C + c0 + c) * HWSZ + gy * WW + gx];
            xs[c][rr * 18 + cc] = v;
        }
    }
    __syncthreads();

    float acc[2][18];
#pragma unroll
    for (int q = 0; q < 2; ++q)
#pragma unroll
        for (int o = 0; o < 18; ++o) acc[q][o] = 0.f;

    for (int c = 0; c < 16; ++c) {
#pragma unroll
        for (int tap = 0; tap < 9; ++tap) {
            int ky = tap / 3, kx = tap % 3;
            float xv0 = xs[c][(py + ky) * 18 + px + kx];
            float xv1 = xs[c][(py + 8 + ky) * 18 + px + kx];
            const float* wrow = &ws[(c * 9 + tap) * 18];
#pragma unroll
            for (int o = 0; o < 18; ++o) {
                float w = wrow[o];
                acc[0][o] += w * xv0;
                acc[1][o] += w * xv1;
            }
        }
    }

    float* pp = g_offp + (long)ch * (BATCH * 18 * HWSZ);
#pragma unroll
    for (int q = 0; q < 2; ++q) {
        int row = ty0 + py + q * 8;
#pragma unroll
        for (int o = 0; o < 18; ++o)
            pp[((long)b * 18 + o) * HWSZ + row * WW + tx0 + px] = acc[q][o];
    }
}

__global__ void offset_reduce_kernel(const float* __restrict__ ob, int CH)
{
    int idx = blockIdx.x * blockDim.x + threadIdx.x;
    const int total = BATCH * 18 * HWSZ;
    if (idx >= total) return;
    int o = (idx / HWSZ) % 18;
    float s = ob[o];
    for (int c = 0; c < CH; ++c)
        s += g_offp[(long)c * total + idx];
    g_off[idx] = s;
}

// ---------------- fused HWC gather + HMMA bf16x3 GEMM (k64 super-chunks) -----
// smem map: weights 9216 | packed idx 2304 | A 2x32768 | B 2x16384 = 109824 B
#define SM_W4 0
#define SM_J  9216
#define SM_A  11520
#define A_MAT 16384
#define A_BUF (2 * A_MAT)            // hi+lo, 32768
#define SM_B  (SM_A + 2 * A_BUF)     // 77056
#define B_MAT 8192
#define B_BUF (2 * B_MAT)            // 16384
#define FGEMM_SMEM (SM_B + 2 * B_BUF) // 109824

template<int C, int KTOT, int NSC, int SEL>
__global__ __launch_bounds__(256, 2)
void fused_gemm_kernel(float* __restrict__ dout)
{
    extern __shared__ char sm[];
    float4*   sw4 = (float4*)(sm + SM_W4);
    unsigned* sjp = (unsigned*)(sm + SM_J);

    const __nv_bfloat16* Ah = SEL ? g_w2h : g_w1h;
    const __nv_bfloat16* Al = SEL ? g_w2l : g_w1l;
    const float* bias       = SEL ? g_b2  : g_b1;
    const float* src        = SEL ? g_h1  : g_xt;   // HWC

    const int tid = threadIdx.x;
    const int warp = tid >> 5, lane = tid & 31;
    const int mbase = (warp >> 1) * 32;
    const int nbase = (warp & 1) * 32;
    const int b = blockIdx.y, j0 = blockIdx.x * 64;
    const unsigned sb = smem_u32(sm);

    // ---- precompute bilinear weights/packed indices for 64 px x 9 taps ----
    for (int i = tid; i < 576; i += 256) {
        int n = i >> 6, pxl = i & 63;
        int pix = j0 + pxl;
        int hh = pix >> 7, ww = pix & 127;
        float offy = g_off[(b * 18 + n)     * HWSZ + pix];
        float offx = g_off[(b * 18 + 9 + n) * HWSZ + pix];
        float py = offy + (float)(n / 3 - 1) + (float)(hh + 1);
        float px = offx + (float)(n % 3 - 1) + (float)(ww + 1);
        const float hiB = 129.f;
        py = fminf(fmaxf(py, 0.f), hiB);
        px = fminf(fmaxf(px, 0.f), hiB);
        float fy = floorf(py), fx = floorf(px);
        float qy1 = fminf(fy + 1.f, hiB), qx1 = fminf(fx + 1.f, hiB);
        float dy0 = 1.f + (fy - py), dy1 = 1.f - (qy1 - py);
        float dx0 = 1.f + (fx - px), dx1 = 1.f - (qx1 - px);
        int iy0 = (int)fy - 1, ix0 = (int)fx - 1;
        int iy1 = (int)qy1 - 1, ix1 = (int)qx1 - 1;
        bool vy0 = (unsigned)iy0 < (unsigned)HH, vy1 = (unsigned)iy1 < (unsigned)HH;
        bool vx0 = (unsigned)ix0 < (unsigned)WW, vx1 = (unsigned)ix1 < (unsigned)WW;
        float w00 = (vy0 && vx0) ? dy0 * dx0 : 0.f;
        float w01 = (vy0 && vx1) ? dy0 * dx1 : 0.f;
        float w10 = (vy1 && vx0) ? dy1 * dx0 : 0.f;
        float w11 = (vy1 && vx1) ? dy1 * dx1 : 0.f;
        int cy0 = min(max(iy0, 0), HH - 1), cy1 = min(max(iy1, 0), HH - 1);
        int cx0 = min(max(ix0, 0), WW - 1), cx1 = min(max(ix1, 0), WW - 1);
        sw4[i] = make_float4(w00, w01, w10, w11);
        sjp[i] = (unsigned)(cy0 * WW + cx0)
               | ((unsigned)(cx1 > cx0) << 30)
               | ((unsigned)(cy1 > cy0) << 31);
    }

    float d[2][4][4];
#pragma unroll
    for (int mt = 0; mt < 2; ++mt)
#pragma unroll
        for (int nt = 0; nt < 4; ++nt)
#pragma unroll
            for (int q = 0; q < 4; ++q) d[mt][nt][q] = 0.f;

    const int half = lane >> 4;            // pixel within pair
    const int l16  = lane & 15;            // channel-group lane
    const float* srcb = src + (long)b * HWSZ * C;
    const float* xtb  = g_xt + (long)b * HWSZ * CIN;

    auto storePair = [&](char* Bb, int pxL, float4 v) {
        unsigned h0 = pack_bf2(v.x, v.y), h1p = pack_bf2(v.z, v.w);
        unsigned l0 = pack_bf2(lo_of(v.x), lo_of(v.y));
        unsigned l1p = pack_bf2(lo_of(v.z), lo_of(v.w));
        unsigned col = ((unsigned)l16 * 8u) ^ ((unsigned)(pxL & 7) * 16u);
        *(uint2*)(Bb + pxL * 128 + col)         = make_uint2(h0, h1p);
        *(uint2*)(Bb + B_MAT + pxL * 128 + col) = make_uint2(l0, l1p);
    };

    auto gatherStore = [&](int sc, int buf) {
        char* Bb = sm + SM_B + buf * B_BUF;
        if (SEL == 1 && sc == NSC - 1) {     // identity super-chunk (k2 only)
#pragma unroll
            for (int q = 0; q < 4; ++q) {
                int pxL = warp * 8 + q * 2 + half;
                float4 v = *(const float4*)(xtb + (long)(j0 + pxL) * CIN + l16 * 4);
                storePair(Bb, pxL, v);
            }
        } else {
            const int n    = (C == 64) ? sc : (sc >> 1);
            const int c0sc = (C == 64) ? 0  : ((sc & 1) << 6);
            const int lch  = c0sc + l16 * 4;
#pragma unroll
            for (int q = 0; q < 4; ++q) {
                int pxL = warp * 8 + q * 2 + half;
                int pi = (n << 6) | pxL;
                float4 wv = sw4[pi];
                unsigned jj = sjp[pi];
                int j00 = (int)(jj & 0xFFFF);
                int dx = (int)((jj >> 30) & 1u);
                int dy = (int)(jj >> 31) << 7;
                const float4 a4 = *(const float4*)(srcb + (long)j00 * C + lch);
                const float4 b4 = *(const float4*)(srcb + (long)(j00 + dx) * C + lch);
                const float4 c4 = *(const float4*)(srcb + (long)(j00 + dy) * C + lch);
                const float4 e4 = *(const float4*)(srcb + (long)(j00 + dy + dx) * C + lch);
                float4 v;
                v.x = wv.x * a4.x + wv.y * b4.x + wv.z * c4.x + wv.w * e4.x;
                v.y = wv.x * a4.y + wv.y * b4.y + wv.z * c4.y + wv.w * e4.y;
                v.z = wv.x * a4.z + wv.y * b4.z + wv.z * c4.z + wv.w * e4.z;
                v.w = wv.x * a4.w + wv.y * b4.w + wv.z * c4.w + wv.w * e4.w;
                storePair(Bb, pxL, v);
            }
        }
    };

    auto loadA = [&](int sc, int buf) {
        int r = tid & 127, hs = tid >> 7;
        unsigned drow = sb + SM_A + buf * A_BUF + r * 128;
        const __nv_bfloat16* sh = Ah + (long)r * KTOT + sc * 64 + hs * 32;
        const __nv_bfloat16* sl = Al + (long)r * KTOT + sc * 64 + hs * 32;
        unsigned rs = (unsigned)(r & 7) * 16u;
#pragma unroll
        for (int j = 0; j < 4; ++j) {
            unsigned col = ((unsigned)(hs * 4 + j) * 16u) ^ rs;
            cp16(drow + col,         sh + j * 8);
            cp16(drow + A_MAT + col, sl + j * 8);
        }
        cp_commit();
    };

    const unsigned a_row = (unsigned)(mbase + (lane & 15));
    const unsigned a_kh  = (unsigned)((lane >> 4) & 1) * 16u;
    const unsigned b_row = (unsigned)(nbase + (lane & 7) + (((lane >> 4) & 1) << 3));
    const unsigned b_kh  = (unsigned)((lane >> 3) & 1) * 16u;

    __syncthreads();          // precomp visible
    loadA(0, 0);
    gatherStore(0, 0);

    for (int sc = 0; sc < NSC; ++sc) {
        const int buf = sc & 1;
        cp_wait0();
        __syncthreads();
        if (sc + 1 < NSC) {
            loadA(sc + 1, buf ^ 1);
            gatherStore(sc + 1, buf ^ 1);
        }
        unsigned abase = sb + SM_A + buf * A_BUF;
        unsigned bbase = sb + SM_B + buf * B_BUF;
#pragma unroll
        for (int kk4 = 0; kk4 < 4; ++kk4) {
            unsigned ah[2][4], al[2][4], bh[2][4], bl[2][4];
#pragma unroll
            for (int mt = 0; mt < 2; ++mt) {
                unsigned row = a_row + mt * 16u;
                unsigned col = (kk4 * 32u + a_kh) ^ ((row & 7u) * 16u);
                unsigned addr = abase + row * 128u + col;
                ldm_x4(addr, ah[mt]);
                ldm_x4(addr + A_MAT, al[mt]);
            }
#pragma unroll
            for (int np = 0; np < 2; ++np) {
                unsigned row = b_row + np * 16u;
                unsigned col = (kk4 * 32u + b_kh) ^ ((row & 7u) * 16u);
                unsigned addr = bbase + row * 128u + col;
                ldm_x4(addr, bh[np]);
                ldm_x4(addr + B_MAT, bl[np]);
            }
#pragma unroll
            for (int mt = 0; mt < 2; ++mt) {
#pragma unroll
                for (int nt = 0; nt < 4; ++nt) {
                    int np = nt >> 1, rp = (nt & 1) * 2;
                    mma16816(d[mt][nt], ah[mt], bh[np][rp], bh[np][rp + 1]);
                    mma16816(d[mt][nt], ah[mt], bl[np][rp], bl[np][rp + 1]);
                    mma16816(d[mt][nt], al[mt], bh[np][rp], bh[np][rp + 1]);
                }
            }
        }
    }

    // epilogue: bias + relu
    const int qr = lane >> 2;
    const int qc = (lane & 3) * 2;
#pragma unroll
    for (int mt = 0; mt < 2; ++mt) {
        int o0 = mbase + mt * 16 + qr;
        int o1 = o0 + 8;
        float bs0 = bias[o0], bs1 = bias[o1];
#pragma unroll
        for (int nt = 0; nt < 4; ++nt) {
            float* acc = d[mt][nt];
            int p0 = j0 + nbase + qc + nt * 8, p1 = p0 + 1;
            if (SEL == 0) {
                float* hb = g_h1 + (long)b * HWSZ * COUT;
                hb[(long)p0 * COUT + o0] = fmaxf(acc[0] + bs0, 0.f);
                hb[(long)p1 * COUT + o0] = fmaxf(acc[1] + bs0, 0.f);
                hb[(long)p0 * COUT + o1] = fmaxf(acc[2] + bs1, 0.f);
                hb[(long)p1 * COUT + o1] = fmaxf(acc[3] + bs1, 0.f);
            } else {
                float* row0 = dout + ((long)b * COUT + o0) * HWSZ + p0;
                float* row1 = dout + ((long)b * COUT + o1) * HWSZ + p0;
                *(float2*)row0 = make_float2(fmaxf(acc[0] + bs0, 0.f),
                                             fmaxf(acc[1] + bs0, 0.f));
                *(float2*)row1 = make_float2(fmaxf(acc[2] + bs1, 0.f),
                                             fmaxf(acc[3] + bs1, 0.f));
            }
        }
    }
}

// ---------------- launch -----------------------------------------------------
extern "C" void kernel_launch(void* const* d_in, const int* in_sizes, int n_in,
                              void* d_out, int out_size)
{
    const float* x        = (const float*)d_in[0];
    const float* dc1_offw = (const float*)d_in[1];
    const float* dc1_offb = (const float*)d_in[2];
    const float* dc1_w    = (const float*)d_in[3];
    const float* bn1_g    = (const float*)d_in[4];
    const float* bn1_b    = (const float*)d_in[5];
    const float* bn1_m    = (const float*)d_in[6];
    const float* bn1_v    = (const float*)d_in[7];
    const float* dc2_offw = (const float*)d_in[8];
    const float* dc2_offb = (const float*)d_in[9];
    const float* dc2_w    = (const float*)d_in[10];
    const float* bn2_g    = (const float*)d_in[11];
    const float* bn2_b    = (const float*)d_in[12];
    const float* bn2_m    = (const float*)d_in[13];
    const float* bn2_v    = (const float*)d_in[14];
    const float* id_w     = (const float*)d_in[15];
    const float* id_b     = (const float*)d_in[16];
    const float* bn3_g    = (const float*)d_in[17];
    const float* bn3_b    = (const float*)d_in[18];
    const float* bn3_m    = (const float*)d_in[19];
    const float* bn3_v    = (const float*)d_in[20];
    float* out = (float*)d_out;

    auto k1 = fused_gemm_kernel<CIN, K1, 9, 0>;
    auto k2 = fused_gemm_kernel<COUT, K2, 19, 1>;
    cudaFuncSetAttribute(k1, cudaFuncAttributeMaxDynamicSharedMemorySize, FGEMM_SMEM);
    cudaFuncSetAttribute(k2, cudaFuncAttributeMaxDynamicSharedMemorySize, FGEMM_SMEM);

    // launch #1: prep + transpose
    prep_all<<<PREP_BLOCKS + XT_BLOCKS, 256>>>(x, dc1_w, dc2_w, id_w, id_b,
                                               bn1_g, bn1_b, bn1_m, bn1_v,
                                               bn2_g, bn2_b, bn2_m, bn2_v,
                                               bn3_g, bn3_b, bn3_m, bn3_v);

    const int RED_N = BATCH * 18 * HWSZ;

    // layer 1 (#2, #3, #4 — k1 on capture slot)
    offset_partial_kernel<<<dim3(WW / 16, HH / 16, BATCH * (CIN / 16)), 128>>>(
        x, 0, dc1_offw, CIN);
    offset_reduce_kernel<<<(RED_N + 255) / 256, 256>>>(dc1_offb, CIN / 16);
    k1<<<dim3(HWSZ / 64, BATCH), 256, FGEMM_SMEM>>>(out);

    // layer 2
    offset_partial_kernel<<<dim3(WW / 16, HH / 16, BATCH * (COUT / 16)), 128>>>(
        x, 1, dc2_offw, COUT);
    offset_reduce_kernel<<<(RED_N + 255) / 256, 256>>>(dc2_offb, COUT / 16);
    k2<<<dim3(HWSZ / 64, BATCH), 256, FGEMM_SMEM>>>(out);
}

// round 14
// speedup vs baseline: 1.0429x; 1.0429x over previous
#include <cuda_runtime.h>
#include <cuda_bf16.h>
#include <math.h>

#define BATCH 2
#define CIN   64
#define COUT  128
#define HH    128
#define WW    128
#define HWSZ  (HH*WW)          // 16384
#define K1    576              // 9*64
#define K2C   1152             // 9*128
#define K2    1216             // + 64 identity rows

// ---------------- scratch (static device globals) ----------------------------
__device__ float g_off[BATCH * 18 * HWSZ];
__device__ float g_offp[8 * BATCH * 18 * HWSZ];             // per-chunk partials
__device__ float g_h1 [BATCH * COUT * HWSZ];
__device__ __nv_bfloat16 g_w1h[COUT * K1], g_w1l[COUT * K1];
__device__ __nv_bfloat16 g_w2h[COUT * K2], g_w2l[COUT * K2];
__device__ float g_b1[COUT], g_b2[COUT];

// ---------------- PTX helpers (sm_80-era only; compute_103-safe) -------------
__device__ __forceinline__ unsigned smem_u32(const void* p) {
    unsigned a;
    asm("{ .reg .u64 t; cvta.to.shared.u64 t, %1; cvt.u32.u64 %0, t; }"
        : "=r"(a) : "l"(p));
    return a;
}
__device__ __forceinline__ void cp16(unsigned dst, const void* src) {
    asm volatile("cp.async.cg.shared.global [%0], [%1], 16;"
                 :: "r"(dst), "l"(src) : "memory");
}
__device__ __forceinline__ void cp_commit() {
    asm volatile("cp.async.commit_group;" ::: "memory");
}
__device__ __forceinline__ void cp_wait0() {
    asm volatile("cp.async.wait_group 0;" ::: "memory");
}
__device__ __forceinline__ void bar_sync(int id, int cnt) {
    asm volatile("bar.sync %0, %1;" :: "r"(id), "r"(cnt) : "memory");
}
__device__ __forceinline__ void bar_arrive(int id, int cnt) {
    asm volatile("bar.arrive %0, %1;" :: "r"(id), "r"(cnt) : "memory");
}
__device__ __forceinline__ void ldm_x4(unsigned a, unsigned r[4]) {
    asm volatile("ldmatrix.sync.aligned.m8n8.x4.shared.b16 {%0,%1,%2,%3}, [%4];"
                 : "=r"(r[0]), "=r"(r[1]), "=r"(r[2]), "=r"(r[3]) : "r"(a));
}
__device__ __forceinline__ void mma16816(float d[4], const unsigned a[4],
                                         unsigned b0, unsigned b1) {
    asm volatile(
        "mma.sync.aligned.m16n8k16.row.col.f32.bf16.bf16.f32 "
        "{%0,%1,%2,%3}, {%4,%5,%6,%7}, {%8,%9}, {%0,%1,%2,%3};"
        : "+f"(d[0]), "+f"(d[1]), "+f"(d[2]), "+f"(d[3])
        : "r"(a[0]), "r"(a[1]), "r"(a[2]), "r"(a[3]), "r"(b0), "r"(b1));
}
__device__ __forceinline__ unsigned pack_bf2(float a, float b) {
    return (unsigned)__bfloat16_as_ushort(__float2bfloat16(a)) |
           ((unsigned)__bfloat16_as_ushort(__float2bfloat16(b)) << 16);
}
__device__ __forceinline__ float lo_of(float v) {
    return v - __bfloat162float(__float2bfloat16(v));
}

// ---------------- merged weight/bias prep ------------------------------------
__device__ __forceinline__ float bn_scale(const float* g, const float* v, int o) {
    return g[o] * rsqrtf(v[o] + 1e-5f);
}
__device__ __forceinline__ void split_store(__nv_bfloat16* hd, __nv_bfloat16* ld,
                                            long i, float v) {
    __nv_bfloat16 h = __float2bfloat16(v);
    hd[i] = h;
    ld[i] = __float2bfloat16(v - __bfloat162float(h));
}

__global__ void prep_all(const float* __restrict__ dc1_w,
                         const float* __restrict__ dc2_w,
                         const float* __restrict__ id_w,
                         const float* __restrict__ id_b,
                         const float* __restrict__ bn1_g, const float* __restrict__ bn1_b,
                         const float* __restrict__ bn1_m, const float* __restrict__ bn1_v,
                         const float* __restrict__ bn2_g, const float* __restrict__ bn2_b,
                         const float* __restrict__ bn2_m, const float* __restrict__ bn2_v,
                         const float* __restrict__ bn3_g, const float* __restrict__ bn3_b,
                         const float* __restrict__ bn3_m, const float* __restrict__ bn3_v)
{
    int idx = blockIdx.x * blockDim.x + threadIdx.x;
    if (idx < COUT) {
        int o = idx;
        float s1 = bn_scale(bn1_g, bn1_v, o);
        float s2 = bn_scale(bn2_g, bn2_v, o);
        float s3 = bn_scale(bn3_g, bn3_v, o);
        g_b1[o] = bn1_b[o] - bn1_m[o] * s1;
        g_b2[o] = (bn2_b[o] - bn2_m[o] * s2) + id_b[o] * s3 + (bn3_b[o] - bn3_m[o] * s3);
    }
    const int n1 = COUT * K1, n2 = COUT * K2C, n3 = COUT * CIN;
    if (idx < n1) {
        int o = idx / K1, kk = idx % K1;
        int c = kk / 9, n = kk % 9;
        float v = dc1_w[idx] * bn_scale(bn1_g, bn1_v, o);
        split_store(g_w1h, g_w1l, (long)o * K1 + n * CIN + c, v);
    } else if (idx < n1 + n2) {
        int r = idx - n1;
        int o = r / K2C, kk = r % K2C;
        int c = kk / 9, n = kk % 9;
        float v = dc2_w[r] * bn_scale(bn2_g, bn2_v, o);
        split_store(g_w2h, g_w2l, (long)o * K2 + n * COUT + c, v);
    } else if (idx < n1 + n2 + n3) {
        int r = idx - n1 - n2;
        int o = r / CIN, c = r % CIN;
        float v = id_w[r] * bn_scale(bn3_g, bn3_v, o);
        split_store(g_w2h, g_w2l, (long)o * K2 + K2C + c, v);
    }
}

// ---------------- offset conv: smem-tiled partial conv -----------------------
__global__ __launch_bounds__(128)
void offset_partial_kernel(const float* __restrict__ xext, int use_h1,
                           const float* __restrict__ ow, int C)
{
    __shared__ float xs[16][324];
    __shared__ float ws[16 * 9 * 18];
    const float* x = use_h1 ? g_h1 : xext;
    const int CH = C / 16;
    const int z = blockIdx.z;
    const int b = z / CH, ch = z % CH, c0 = ch * 16;
    const int tx0 = blockIdx.x * 16, ty0 = blockIdx.y * 16;
    const int t = threadIdx.x;
    const int py = t >> 4, px = t & 15;

    for (int i = t; i < 16 * 162; i += 128) {
        int c = i / 162, r = i % 162, tap = r / 18, o = r % 18;
        ws[i] = ow[o * C * 9 + (c0 + c) * 9 + tap];
    }
    for (int i = t; i < 16 * 324; i += 128) {
        int c = i / 324, rr = (i % 324) / 18, cc = i % 18;
        int gy = ty0 - 1 + rr, gx = tx0 - 1 + cc;
        float v = 0.f;
        if ((unsigned)gy < (unsigned)HH && (unsigned)gx < (unsigned)WW)
            v = x[((long)b * C + c0 + c) * HWSZ + gy * WW + gx];
        xs[c][rr * 18 + cc] = v;
    }
    __syncthreads();

    float acc[2][18];
#pragma unroll
    for (int q = 0; q < 2; ++q)
#pragma unroll
        for (int o = 0; o < 18; ++o) acc[q][o] = 0.f;

    for (int c = 0; c < 16; ++c) {
#pragma unroll
        for (int tap = 0; tap < 9; ++tap) {
            int ky = tap / 3, kx = tap % 3;
            float xv0 = xs[c][(py + ky) * 18 + px + kx];
            float xv1 = xs[c][(py + 8 + ky) * 18 + px + kx];
            const float* wrow = &ws[(c * 9 + tap) * 18];
#pragma unroll
            for (int o = 0; o < 18; ++o) {
                float w = wrow[o];
                acc[0][o] += w * xv0;
                acc[1][o] += w * xv1;
            }
        }
    }

    float* pp = g_offp + (long)ch * (BATCH * 18 * HWSZ);
#pragma unroll
    for (int q = 0; q < 2; ++q) {
        int row = ty0 + py + q * 8;
#pragma unroll
        for (int o = 0; o < 18; ++o)
            pp[((long)b * 18 + o) * HWSZ + row * WW + tx0 + px] = acc[q][o];
    }
}

__global__ void offset_reduce_kernel(const float* __restrict__ ob, int CH)
{
    int idx = blockIdx.x * blockDim.x + threadIdx.x;
    const int total = BATCH * 18 * HWSZ;
    if (idx >= total) return;
    int o = (idx / HWSZ) % 18;
    float s = ob[o];
    for (int c = 0; c < CH; ++c)
        s += g_offp[(long)c * total + idx];
    g_off[idx] = s;
}

// ---------------- fused sample + HMMA bf16x3 GEMM, warp-specialized ----------
// 384 threads: warps 0-7 consumers (MMA), warps 8-11 producers (gather + A cp).
// 3-stage smem ring; named barriers: full = 1+s, empty = 4+s, count = 384.
#define NSTG 3
#define ROWB2 48
#define A_MAT (128 * ROWB2)           // 6144
#define A_BUF (2 * A_MAT)             // 12288 (hi+lo)
#define B_MAT (64 * ROWB2)            // 3072
#define B_BUF (2 * B_MAT)             // 6144
#define SM_W4 0
#define SM_J4 9216
#define SM_A  18432
#define SM_B  (SM_A + NSTG * A_BUF)   // 55296
#define FGEMM_SMEM (SM_B + NSTG * B_BUF) // 73728

template<int C, int KTOT, int NCH, int CSH, int IDST, int SEL>
__global__ __launch_bounds__(384)
void fused_gemm_kernel(const float* __restrict__ xptr, float* __restrict__ dout)
{
    extern __shared__ char sm[];
    float4* sw4 = (float4*)(sm + SM_W4);
    int4*   sj4 = (int4*)(sm + SM_J4);

    const __nv_bfloat16* Ah = SEL ? g_w2h : g_w1h;
    const __nv_bfloat16* Al = SEL ? g_w2l : g_w1l;
    const float* bias       = SEL ? g_b2  : g_b1;
    float* Cp               = SEL ? dout  : g_h1;
    const float* src        = SEL ? g_h1  : xptr;

    const int tid = threadIdx.x;
    const int warp = tid >> 5, lane = tid & 31;
    const int b = blockIdx.y, j0 = blockIdx.x * 64;
    const unsigned sb = smem_u32(sm);

    // ---- precompute bilinear weights/indices for 64 px x 9 taps ----
    for (int i = tid; i < 576; i += 384) {
        int n = i / 64, pxl = i & 63;
        int pix = j0 + pxl;
        int hh = pix >> 7, ww = pix & 127;
        float offy = g_off[(b * 18 + n)     * HWSZ + pix];
        float offx = g_off[(b * 18 + 9 + n) * HWSZ + pix];
        float py = offy + (float)(n / 3 - 1) + (float)(hh + 1);
        float px = offx + (float)(n % 3 - 1) + (float)(ww + 1);
        const float hiB = 129.f;
        py = fminf(fmaxf(py, 0.f), hiB);
        px = fminf(fmaxf(px, 0.f), hiB);
        float fy = floorf(py), fx = floorf(px);
        float qy1 = fminf(fy + 1.f, hiB), qx1 = fminf(fx + 1.f, hiB);
        float dy0 = 1.f + (fy - py), dy1 = 1.f - (qy1 - py);
        float dx0 = 1.f + (fx - px), dx1 = 1.f - (qx1 - px);
        int iy0 = (int)fy - 1, ix0 = (int)fx - 1;
        int iy1 = (int)qy1 - 1, ix1 = (int)qx1 - 1;
        bool vy0 = (unsigned)iy0 < (unsigned)HH, vy1 = (unsigned)iy1 < (unsigned)HH;
        bool vx0 = (unsigned)ix0 < (unsigned)WW, vx1 = (unsigned)ix1 < (unsigned)WW;
        float w00 = (vy0 && vx0) ? dy0 * dx0 : 0.f;
        float w01 = (vy0 && vx1) ? dy0 * dx1 : 0.f;
        float w10 = (vy1 && vx0) ? dy1 * dx0 : 0.f;
        float w11 = (vy1 && vx1) ? dy1 * dx1 : 0.f;
        int cy0 = min(max(iy0, 0), HH - 1), cy1 = min(max(iy1, 0), HH - 1);
        int cx0 = min(max(ix0, 0), WW - 1), cx1 = min(max(ix1, 0), WW - 1);
        sw4[i] = make_float4(w00, w01, w10, w11);
        sj4[i] = make_int4(cy0 * WW + cx0, cy0 * WW + cx1,
                           cy1 * WW + cx0, cy1 * WW + cx1);
    }
    __syncthreads();

    if (warp < 8) {
        // ================= CONSUMER =================
        const int mbase = (warp >> 1) * 32;
        const int nbase = (warp & 1) * 32;
        float d[2][4][4];
#pragma unroll
        for (int mt = 0; mt < 2; ++mt)
#pragma unroll
            for (int nt = 0; nt < 4; ++nt)
#pragma unroll
                for (int q = 0; q < 4; ++q) d[mt][nt][q] = 0.f;

        const unsigned a_off = (unsigned)(mbase + (lane & 15)) * ROWB2 +
                               (unsigned)((lane >> 4) & 1) * 16u;
        const unsigned b_off = (unsigned)(nbase + (lane & 7) + (((lane >> 4) & 1) << 3)) * ROWB2 +
                               (unsigned)((lane >> 3) & 1) * 16u;

        for (int ch = 0; ch < NCH; ++ch) {
            const int s = ch % NSTG;
            bar_sync(1 + s, 384);
            unsigned abase = sb + SM_A + s * A_BUF;
            unsigned bbase = sb + SM_B + s * B_BUF;
            unsigned ah[2][4], al[2][4], bh[2][4], bl[2][4];
#pragma unroll
            for (int mt = 0; mt < 2; ++mt) {
                unsigned addr = abase + a_off + mt * 16u * ROWB2;
                ldm_x4(addr, ah[mt]);
                ldm_x4(addr + A_MAT, al[mt]);
            }
#pragma unroll
            for (int np = 0; np < 2; ++np) {
                unsigned addr = bbase + b_off + np * 16u * ROWB2;
                ldm_x4(addr, bh[np]);
                ldm_x4(addr + B_MAT, bl[np]);
            }
#pragma unroll
            for (int mt = 0; mt < 2; ++mt) {
#pragma unroll
                for (int nt = 0; nt < 4; ++nt) {
                    int np = nt >> 1, rp = (nt & 1) * 2;
                    mma16816(d[mt][nt], ah[mt], bh[np][rp], bh[np][rp + 1]);
                    mma16816(d[mt][nt], ah[mt], bl[np][rp], bl[np][rp + 1]);
                    mma16816(d[mt][nt], al[mt], bh[np][rp], bh[np][rp + 1]);
                }
            }
            bar_arrive(4 + s, 384);
        }

        // epilogue: bias + relu
        const int qr = lane >> 2;
        const int qc = (lane & 3) * 2;
#pragma unroll
        for (int mt = 0; mt < 2; ++mt) {
            int o0 = mbase + mt * 16 + qr;
            int o1 = o0 + 8;
            float bs0 = bias[o0], bs1 = bias[o1];
            float* row0 = Cp + ((long)b * COUT + o0) * HWSZ + j0 + nbase + qc;
            float* row1 = Cp + ((long)b * COUT + o1) * HWSZ + j0 + nbase + qc;
#pragma unroll
            for (int nt = 0; nt < 4; ++nt) {
                float* acc = d[mt][nt];
                *(float2*)(row0 + nt * 8) =
                    make_float2(fmaxf(acc[0] + bs0, 0.f), fmaxf(acc[1] + bs0, 0.f));
                *(float2*)(row1 + nt * 8) =
                    make_float2(fmaxf(acc[2] + bs1, 0.f), fmaxf(acc[3] + bs1, 0.f));
            }
        }
    } else {
        // ================= PRODUCER =================
        const int pt   = tid - 256;          // 0..127
        const int pxl  = pt & 63;
        const int cg0  = pt >> 6;            // 0..1 -> this thread covers cg0, cg0+2
        const int pix  = j0 + pxl;
        const float* srcb = src + (long)b * C * HWSZ;
        const float* xb   = xptr + (long)b * CIN * HWSZ;

        for (int ch = 0; ch < NCH; ++ch) {
            const int s = ch % NSTG;
            if (ch >= NSTG) bar_sync(4 + s, 384);

            // issue A cp.async first (latency overlapped by gathers)
            {
                int k0 = ch * 16;
                unsigned dst = sb + SM_A + s * A_BUF + pt * ROWB2;
                const __nv_bfloat16* sh = Ah + (long)pt * KTOT + k0;
                const __nv_bfloat16* sl = Al + (long)pt * KTOT + k0;
                cp16(dst,              sh);
                cp16(dst + 16,         sh + 8);
                cp16(dst + A_MAT,      sl);
                cp16(dst + A_MAT + 16, sl + 8);
                cp_commit();
            }

            float v0[4], v1[4];
            if (ch < IDST) {
                int n = ch >> CSH, cb = (ch & ((1 << CSH) - 1)) * 16;
                int pi = (n << 6) | pxl;
                float4 wv = sw4[pi];
                int4 jv = sj4[pi];
                int cA = cb + cg0 * 4;
                int cB = cb + (cg0 + 2) * 4;
#pragma unroll
                for (int u = 0; u < 4; ++u) {
                    const float* pc = srcb + (long)(cA + u) * HWSZ;
                    v0[u] = wv.x * pc[jv.x] + wv.y * pc[jv.y]
                          + wv.z * pc[jv.z] + wv.w * pc[jv.w];
                }
#pragma unroll
                for (int u = 0; u < 4; ++u) {
                    const float* pc = srcb + (long)(cB + u) * HWSZ;
                    v1[u] = wv.x * pc[jv.x] + wv.y * pc[jv.y]
                          + wv.z * pc[jv.z] + wv.w * pc[jv.w];
                }
            } else {
                int cb = (ch - IDST) * 16;
#pragma unroll
                for (int u = 0; u < 4; ++u)
                    v0[u] = xb[(long)(cb + cg0 * 4 + u) * HWSZ + pix];
#pragma unroll
                for (int u = 0; u < 4; ++u)
                    v1[u] = xb[(long)(cb + (cg0 + 2) * 4 + u) * HWSZ + pix];
            }

            char* base = sm + SM_B + s * B_BUF + pxl * ROWB2;
            {
                unsigned h0 = pack_bf2(v0[0], v0[1]), h1 = pack_bf2(v0[2], v0[3]);
                unsigned l0 = pack_bf2(lo_of(v0[0]), lo_of(v0[1]));
                unsigned l1 = pack_bf2(lo_of(v0[2]), lo_of(v0[3]));
                *(uint2*)(base + cg0 * 8)         = make_uint2(h0, h1);
                *(uint2*)(base + B_MAT + cg0 * 8) = make_uint2(l0, l1);
            }
            {
                unsigned h0 = pack_bf2(v1[0], v1[1]), h1 = pack_bf2(v1[2], v1[3]);
                unsigned l0 = pack_bf2(lo_of(v1[0]), lo_of(v1[1]));
                unsigned l1 = pack_bf2(lo_of(v1[2]), lo_of(v1[3]));
                *(uint2*)(base + (cg0 + 2) * 8)         = make_uint2(h0, h1);
                *(uint2*)(base + B_MAT + (cg0 + 2) * 8) = make_uint2(l0, l1);
            }

            cp_wait0();
            bar_arrive(1 + s, 384);
        }
    }
}

// ---------------- launch -----------------------------------------------------
extern "C" void kernel_launch(void* const* d_in, const int* in_sizes, int n_in,
                              void* d_out, int out_size)
{
    const float* x        = (const float*)d_in[0];
    const float* dc1_offw = (const float*)d_in[1];
    const float* dc1_offb = (const float*)d_in[2];
    const float* dc1_w    = (const float*)d_in[3];
    const float* bn1_g    = (const float*)d_in[4];
    const float* bn1_b    = (const float*)d_in[5];
    const float* bn1_m    = (const float*)d_in[6];
    const float* bn1_v    = (const float*)d_in[7];
    const float* dc2_offw = (const float*)d_in[8];
    const float* dc2_offb = (const float*)d_in[9];
    const float* dc2_w    = (const float*)d_in[10];
    const float* bn2_g    = (const float*)d_in[11];
    const float* bn2_b    = (const float*)d_in[12];
    const float* bn2_m    = (const float*)d_in[13];
    const float* bn2_v    = (const float*)d_in[14];
    const float* id_w     = (const float*)d_in[15];
    const float* id_b     = (const float*)d_in[16];
    const float* bn3_g    = (const float*)d_in[17];
    const float* bn3_b    = (const float*)d_in[18];
    const float* bn3_m    = (const float*)d_in[19];
    const float* bn3_v    = (const float*)d_in[20];
    float* out = (float*)d_out;

    auto k1 = fused_gemm_kernel<CIN, K1, 36, 2, 36, 0>;
    auto k2 = fused_gemm_kernel<COUT, K2, 76, 3, 72, 1>;
    cudaFuncSetAttribute(k1, cudaFuncAttributeMaxDynamicSharedMemorySize, FGEMM_SMEM);
    cudaFuncSetAttribute(k2, cudaFuncAttributeMaxDynamicSharedMemorySize, FGEMM_SMEM);

    // launch #1: prep
    {
        int total = COUT * K1 + COUT * K2C + COUT * CIN;
        prep_all<<<(total + 255) / 256, 256>>>(dc1_w, dc2_w, id_w, id_b,
                                               bn1_g, bn1_b, bn1_m, bn1_v,
                                               bn2_g, bn2_b, bn2_m, bn2_v,
                                               bn3_g, bn3_b, bn3_m, bn3_v);
    }

    const int RED_N = BATCH * 18 * HWSZ;

    // layer 1 (#2, #3, #4 — k1 on capture slot)
    offset_partial_kernel<<<dim3(WW / 16, HH / 16, BATCH * (CIN / 16)), 128>>>(
        x, 0, dc1_offw, CIN);
    offset_reduce_kernel<<<(RED_N + 255) / 256, 256>>>(dc1_offb, CIN / 16);
    k1<<<dim3(HWSZ / 64, BATCH), 384, FGEMM_SMEM>>>(x, out);

    // layer 2
    offset_partial_kernel<<<dim3(WW / 16, HH / 16, BATCH * (COUT / 16)), 128>>>(
        x, 1, dc2_offw, COUT);
    offset_reduce_kernel<<<(RED_N + 255) / 256, 256>>>(dc2_offb, COUT / 16);
    k2<<<dim3(HWSZ / 64, BATCH), 384, FGEMM_SMEM>>>(x, out);
}

// round 15
// speedup vs baseline: 1.2961x; 1.2428x over previous
#include <cuda_runtime.h>
#include <cuda_bf16.h>
#include <math.h>

#define BATCH 2
#define CIN   64
#define COUT  128
#define HH    128
#define WW    128
#define HWSZ  (HH*WW)          // 16384
#define K1    576              // 9*64
#define K2C   1152             // 9*128
#define K2    1216             // + 64 identity rows

// ---------------- scratch (static device globals) ----------------------------
__device__ float g_offp[8 * BATCH * 18 * HWSZ];             // per-chunk partials
__device__ float g_h1 [BATCH * COUT * HWSZ];
__device__ __nv_bfloat16 g_w1h[COUT * K1], g_w1l[COUT * K1];
__device__ __nv_bfloat16 g_w2h[COUT * K2], g_w2l[COUT * K2];
__device__ float g_b1[COUT], g_b2[COUT];

// ---------------- PTX helpers (sm_80-era only; compute_103-safe) -------------
__device__ __forceinline__ unsigned smem_u32(const void* p) {
    unsigned a;
    asm("{ .reg .u64 t; cvta.to.shared.u64 t, %1; cvt.u32.u64 %0, t; }"
        : "=r"(a) : "l"(p));
    return a;
}
__device__ __forceinline__ void cp16(unsigned dst, const void* src) {
    asm volatile("cp.async.cg.shared.global [%0], [%1], 16;"
                 :: "r"(dst), "l"(src) : "memory");
}
__device__ __forceinline__ void cp_commit() {
    asm volatile("cp.async.commit_group;" ::: "memory");
}
__device__ __forceinline__ void cp_wait0() {
    asm volatile("cp.async.wait_group 0;" ::: "memory");
}
__device__ __forceinline__ void ldm_x4(unsigned a, unsigned r[4]) {
    asm volatile("ldmatrix.sync.aligned.m8n8.x4.shared.b16 {%0,%1,%2,%3}, [%4];"
                 : "=r"(r[0]), "=r"(r[1]), "=r"(r[2]), "=r"(r[3]) : "r"(a));
}
__device__ __forceinline__ void mma16816(float d[4], const unsigned a[4],
                                         unsigned b0, unsigned b1) {
    asm volatile(
        "mma.sync.aligned.m16n8k16.row.col.f32.bf16.bf16.f32 "
        "{%0,%1,%2,%3}, {%4,%5,%6,%7}, {%8,%9}, {%0,%1,%2,%3};"
        : "+f"(d[0]), "+f"(d[1]), "+f"(d[2]), "+f"(d[3])
        : "r"(a[0]), "r"(a[1]), "r"(a[2]), "r"(a[3]), "r"(b0), "r"(b1));
}
__device__ __forceinline__ unsigned pack_bf2(float a, float b) {
    return (unsigned)__bfloat16_as_ushort(__float2bfloat16(a)) |
           ((unsigned)__bfloat16_as_ushort(__float2bfloat16(b)) << 16);
}
__device__ __forceinline__ float lo_of(float v) {
    return v - __bfloat162float(__float2bfloat16(v));
}

// ---------------- merged weight/bias prep ------------------------------------
__device__ __forceinline__ float bn_scale(const float* g, const float* v, int o) {
    return g[o] * rsqrtf(v[o] + 1e-5f);
}
__device__ __forceinline__ void split_store(__nv_bfloat16* hd, __nv_bfloat16* ld,
                                            long i, float v) {
    __nv_bfloat16 h = __float2bfloat16(v);
    hd[i] = h;
    ld[i] = __float2bfloat16(v - __bfloat162float(h));
}

__global__ void prep_all(const float* __restrict__ dc1_w,
                         const float* __restrict__ dc2_w,
                         const float* __restrict__ id_w,
                         const float* __restrict__ id_b,
                         const float* __restrict__ bn1_g, const float* __restrict__ bn1_b,
                         const float* __restrict__ bn1_m, const float* __restrict__ bn1_v,
                         const float* __restrict__ bn2_g, const float* __restrict__ bn2_b,
                         const float* __restrict__ bn2_m, const float* __restrict__ bn2_v,
                         const float* __restrict__ bn3_g, const float* __restrict__ bn3_b,
                         const float* __restrict__ bn3_m, const float* __restrict__ bn3_v)
{
    int idx = blockIdx.x * blockDim.x + threadIdx.x;
    if (idx < COUT) {
        int o = idx;
        float s1 = bn_scale(bn1_g, bn1_v, o);
        float s2 = bn_scale(bn2_g, bn2_v, o);
        float s3 = bn_scale(bn3_g, bn3_v, o);
        g_b1[o] = bn1_b[o] - bn1_m[o] * s1;
        g_b2[o] = (bn2_b[o] - bn2_m[o] * s2) + id_b[o] * s3 + (bn3_b[o] - bn3_m[o] * s3);
    }
    const int n1 = COUT * K1, n2 = COUT * K2C, n3 = COUT * CIN;
    if (idx < n1) {
        int o = idx / K1, kk = idx % K1;
        int c = kk / 9, n = kk % 9;
        float v = dc1_w[idx] * bn_scale(bn1_g, bn1_v, o);
        split_store(g_w1h, g_w1l, (long)o * K1 + n * CIN + c, v);
    } else if (idx < n1 + n2) {
        int r = idx - n1;
        int o = r / K2C, kk = r % K2C;
        int c = kk / 9, n = kk % 9;
        float v = dc2_w[r] * bn_scale(bn2_g, bn2_v, o);
        split_store(g_w2h, g_w2l, (long)o * K2 + n * COUT + c, v);
    } else if (idx < n1 + n2 + n3) {
        int r = idx - n1 - n2;
        int o = r / CIN, c = r % CIN;
        float v = id_w[r] * bn_scale(bn3_g, bn3_v, o);
        split_store(g_w2h, g_w2l, (long)o * K2 + K2C + c, v);
    }
}

// ---------------- offset conv: smem-tiled partial conv -----------------------
__global__ __launch_bounds__(128)
void offset_partial_kernel(const float* __restrict__ xext, int use_h1,
                           const float* __restrict__ ow, int C)
{
    __shared__ float xs[16][324];
    __shared__ float ws[16 * 9 * 18];
    const float* x = use_h1 ? g_h1 : xext;
    const int CH = C / 16;
    const int z = blockIdx.z;
    const int b = z / CH, ch = z % CH, c0 = ch * 16;
    const int tx0 = blockIdx.x * 16, ty0 = blockIdx.y * 16;
    const int t = threadIdx.x;
    const int py = t >> 4, px = t & 15;

    for (int i = t; i < 16 * 162; i += 128) {
        int c = i / 162, r = i % 162, tap = r / 18, o = r % 18;
        ws[i] = ow[o * C * 9 + (c0 + c) * 9 + tap];
    }
    for (int i = t; i < 16 * 324; i += 128) {
        int c = i / 324, rr = (i % 324) / 18, cc = i % 18;
        int gy = ty0 - 1 + rr, gx = tx0 - 1 + cc;
        float v = 0.f;
        if ((unsigned)gy < (unsigned)HH && (unsigned)gx < (unsigned)WW)
            v = x[((long)b * C + c0 + c) * HWSZ + gy * WW + gx];
        xs[c][rr * 18 + cc] = v;
    }
    __syncthreads();

    float acc[2][18];
#pragma unroll
    for (int q = 0; q < 2; ++q)
#pragma unroll
        for (int o = 0; o < 18; ++o) acc[q][o] = 0.f;

    for (int c = 0; c < 16; ++c) {
#pragma unroll
        for (int tap = 0; tap < 9; ++tap) {
            int ky = tap / 3, kx = tap % 3;
            float xv0 = xs[c][(py + ky) * 18 + px + kx];
            float xv1 = xs[c][(py + 8 + ky) * 18 + px + kx];
            const float* wrow = &ws[(c * 9 + tap) * 18];
#pragma unroll
            for (int o = 0; o < 18; ++o) {
                float w = wrow[o];
                acc[0][o] += w * xv0;
                acc[1][o] += w * xv1;
            }
        }
    }

    float* pp = g_offp + (long)ch * (BATCH * 18 * HWSZ);
#pragma unroll
    for (int q = 0; q < 2; ++q) {
        int row = ty0 + py + q * 8;
#pragma unroll
        for (int o = 0; o < 18; ++o)
            pp[((long)b * 18 + o) * HWSZ + row * WW + tx0 + px] = acc[q][o];
    }
}

// ---------------- fused sample + HMMA bf16x3 GEMM, N=128 tiles ---------------
// 256 threads, 8 warps, warp tile 32M x 64N; K-chunks of 16; 2-deep pipeline.
// Offset reduce + bias folded into the per-CTA precomp (reads g_offp planes).
#define ROWB2 48
#define A_MAT (128 * ROWB2)           // 6144
#define A_BUF (2 * A_MAT)             // 12288 (hi+lo)
#define B_MAT (128 * ROWB2)           // 6144
#define B_BUF (2 * B_MAT)             // 12288
#define SM_W4 0
#define SM_J4 18432
#define SM_A  36864
#define SM_B  (SM_A + 2 * A_BUF)      // 61440
#define FGEMM_SMEM (SM_B + 2 * B_BUF) // 86016

template<int C, int KTOT, int NCH, int CSH, int IDST, int SEL, int CHP>
__global__ __launch_bounds__(256, 2)
void fused_gemm_kernel(const float* __restrict__ xptr,
                       const float* __restrict__ offb,
                       float* __restrict__ dout)
{
    extern __shared__ char sm[];
    float4* sw4 = (float4*)(sm + SM_W4);
    int4*   sj4 = (int4*)(sm + SM_J4);

    const __nv_bfloat16* Ah = SEL ? g_w2h : g_w1h;
    const __nv_bfloat16* Al = SEL ? g_w2l : g_w1l;
    const float* bias       = SEL ? g_b2  : g_b1;
    float* Cp               = SEL ? dout  : g_h1;
    const float* src        = SEL ? g_h1  : xptr;

    const int tid = threadIdx.x;
    const int warp = tid >> 5, lane = tid & 31;
    const int mbase = (warp >> 1) * 32;
    const int nbase = (warp & 1) * 64;
    const int b = blockIdx.y, j0 = blockIdx.x * 128;
    const unsigned sb = smem_u32(sm);

    // ---- precomp: fold offset reduce + bias, bilinear weights/indices -------
    // 128 px x 9 taps = 1152 entries
    for (int i = tid; i < 1152; i += 256) {
        int n = i >> 7, pxl = i & 127;
        int pix = j0 + pxl;
        int hh = pix >> 7, ww = pix & 127;
        const int planes = BATCH * 18 * HWSZ;
        float offy = offb[n], offx = offb[9 + n];
        long ybase = (long)(b * 18 + n) * HWSZ + pix;
        long xbase = (long)(b * 18 + 9 + n) * HWSZ + pix;
#pragma unroll
        for (int c = 0; c < CHP; ++c) {
            offy += g_offp[(long)c * planes + ybase];
            offx += g_offp[(long)c * planes + xbase];
        }
        float py = offy + (float)(n / 3 - 1) + (float)(hh + 1);
        float px = offx + (float)(n % 3 - 1) + (float)(ww + 1);
        const float hiB = 129.f;
        py = fminf(fmaxf(py, 0.f), hiB);
        px = fminf(fmaxf(px, 0.f), hiB);
        float fy = floorf(py), fx = floorf(px);
        float qy1 = fminf(fy + 1.f, hiB), qx1 = fminf(fx + 1.f, hiB);
        float dy0 = 1.f + (fy - py), dy1 = 1.f - (qy1 - py);
        float dx0 = 1.f + (fx - px), dx1 = 1.f - (qx1 - px);
        int iy0 = (int)fy - 1, ix0 = (int)fx - 1;
        int iy1 = (int)qy1 - 1, ix1 = (int)qx1 - 1;
        bool vy0 = (unsigned)iy0 < (unsigned)HH, vy1 = (unsigned)iy1 < (unsigned)HH;
        bool vx0 = (unsigned)ix0 < (unsigned)WW, vx1 = (unsigned)ix1 < (unsigned)WW;
        float w00 = (vy0 && vx0) ? dy0 * dx0 : 0.f;
        float w01 = (vy0 && vx1) ? dy0 * dx1 : 0.f;
        float w10 = (vy1 && vx0) ? dy1 * dx0 : 0.f;
        float w11 = (vy1 && vx1) ? dy1 * dx1 : 0.f;
        int cy0 = min(max(iy0, 0), HH - 1), cy1 = min(max(iy1, 0), HH - 1);
        int cx0 = min(max(ix0, 0), WW - 1), cx1 = min(max(ix1, 0), WW - 1);
        sw4[i] = make_float4(w00, w01, w10, w11);
        sj4[i] = make_int4(cy0 * WW + cx0, cy0 * WW + cx1,
                           cy1 * WW + cx0, cy1 * WW + cx1);
    }

    float d[2][8][4];
#pragma unroll
    for (int mt = 0; mt < 2; ++mt)
#pragma unroll
        for (int nt = 0; nt < 8; ++nt)
#pragma unroll
            for (int q = 0; q < 4; ++q) d[mt][nt][q] = 0.f;

    // gather mapping: 32 consecutive pixels per warp; 8 channels per thread
    const int cgrp = tid >> 7;          // 0..1, 8 channels each
    const int pxl  = tid & 127;
    const int pix  = j0 + pxl;
    const float* srcb = src + (long)b * C * HWSZ;
    const float* xb   = xptr + (long)b * CIN * HWSZ;

    float v[8];
    auto gather = [&](int ch) {
        if (ch < IDST) {
            int n = ch >> CSH, c0 = (ch & ((1 << CSH) - 1)) * 16 + cgrp * 8;
            int pi = (n << 7) | pxl;
            float4 wv = sw4[pi];
            int4 jv = sj4[pi];
#pragma unroll
            for (int u = 0; u < 8; ++u) {
                const float* pc = srcb + (long)(c0 + u) * HWSZ;
                v[u] = wv.x * pc[jv.x] + wv.y * pc[jv.y]
                     + wv.z * pc[jv.z] + wv.w * pc[jv.w];
            }
        } else {
            int c0 = (ch - IDST) * 16 + cgrp * 8;
#pragma unroll
            for (int u = 0; u < 8; ++u)
                v[u] = xb[(long)(c0 + u) * HWSZ + pix];
        }
    };
    auto storeB = [&](unsigned p) {
        char* base = sm + SM_B + p * B_BUF + pxl * ROWB2 + cgrp * 16;
#pragma unroll
        for (int g = 0; g < 2; ++g) {
            unsigned h0 = pack_bf2(v[g * 4 + 0], v[g * 4 + 1]);
            unsigned h1 = pack_bf2(v[g * 4 + 2], v[g * 4 + 3]);
            unsigned l0 = pack_bf2(lo_of(v[g * 4 + 0]), lo_of(v[g * 4 + 1]));
            unsigned l1 = pack_bf2(lo_of(v[g * 4 + 2]), lo_of(v[g * 4 + 3]));
            *(uint2*)(base + g * 8)         = make_uint2(h0, h1);
            *(uint2*)(base + B_MAT + g * 8) = make_uint2(l0, l1);
        }
    };
    auto loadA = [&](int ch, unsigned p) {
        int k0 = ch * 16;
        int r = tid >> 1, seg = tid & 1;
        unsigned dst = sb + SM_A + p * A_BUF + r * ROWB2 + seg * 16;
        cp16(dst,         Ah + (long)r * KTOT + k0 + seg * 8);
        cp16(dst + A_MAT, Al + (long)r * KTOT + k0 + seg * 8);
        cp_commit();
    };

    const unsigned a_off = (unsigned)(mbase + (lane & 15)) * ROWB2 +
                           (unsigned)((lane >> 4) & 1) * 16u;
    const unsigned b_off = (unsigned)(nbase + (lane & 7) + (((lane >> 4) & 1) << 3)) * ROWB2 +
                           (unsigned)((lane >> 3) & 1) * 16u;

    __syncthreads();          // precomp visible
    gather(0);
    storeB(0);
    loadA(0, 0);

    unsigned p = 0;
    for (int ch = 0; ch < NCH; ++ch) {
        cp_wait0();
        __syncthreads();
        if (ch + 1 < NCH) {
            gather(ch + 1);
            loadA(ch + 1, p ^ 1);
        }
        {
            unsigned abase = sb + SM_A + p * A_BUF;
            unsigned bbase = sb + SM_B + p * B_BUF;
            unsigned ah[2][4], al[2][4], bh[4][4], bl[4][4];
#pragma unroll
            for (int mt = 0; mt < 2; ++mt) {
                unsigned addr = abase + a_off + mt * 16u * ROWB2;
                ldm_x4(addr, ah[mt]);
                ldm_x4(addr + A_MAT, al[mt]);
            }
#pragma unroll
            for (int np = 0; np < 4; ++np) {
                unsigned addr = bbase + b_off + np * 16u * ROWB2;
                ldm_x4(addr, bh[np]);
                ldm_x4(addr + B_MAT, bl[np]);
            }
#pragma unroll
            for (int mt = 0; mt < 2; ++mt) {
#pragma unroll
                for (int nt = 0; nt < 8; ++nt) {
                    int np = nt >> 1, rp = (nt & 1) * 2;
                    mma16816(d[mt][nt], ah[mt], bh[np][rp], bh[np][rp + 1]);
                    mma16816(d[mt][nt], ah[mt], bl[np][rp], bl[np][rp + 1]);
                    mma16816(d[mt][nt], al[mt], bh[np][rp], bh[np][rp + 1]);
                }
            }
        }
        if (ch + 1 < NCH) storeB(p ^ 1);
        p ^= 1;
    }

    // epilogue: bias + relu
    const int qr = lane >> 2;
    const int qc = (lane & 3) * 2;
#pragma unroll
    for (int mt = 0; mt < 2; ++mt) {
        int o0 = mbase + mt * 16 + qr;
        int o1 = o0 + 8;
        float bs0 = bias[o0], bs1 = bias[o1];
        float* row0 = Cp + ((long)b * COUT + o0) * HWSZ + j0 + nbase + qc;
        float* row1 = Cp + ((long)b * COUT + o1) * HWSZ + j0 + nbase + qc;
#pragma unroll
        for (int nt = 0; nt < 8; ++nt) {
            float* acc = d[mt][nt];
            *(float2*)(row0 + nt * 8) =
                make_float2(fmaxf(acc[0] + bs0, 0.f), fmaxf(acc[1] + bs0, 0.f));
            *(float2*)(row1 + nt * 8) =
                make_float2(fmaxf(acc[2] + bs1, 0.f), fmaxf(acc[3] + bs1, 0.f));
        }
    }
}

// ---------------- launch -----------------------------------------------------
extern "C" void kernel_launch(void* const* d_in, const int* in_sizes, int n_in,
                              void* d_out, int out_size)
{
    const float* x        = (const float*)d_in[0];
    const float* dc1_offw = (const float*)d_in[1];
    const float* dc1_offb = (const float*)d_in[2];
    const float* dc1_w    = (const float*)d_in[3];
    const float* bn1_g    = (const float*)d_in[4];
    const float* bn1_b    = (const float*)d_in[5];
    const float* bn1_m    = (const float*)d_in[6];
    const float* bn1_v    = (const float*)d_in[7];
    const float* dc2_offw = (const float*)d_in[8];
    const float* dc2_offb = (const float*)d_in[9];
    const float* dc2_w    = (const float*)d_in[10];
    const float* bn2_g    = (const float*)d_in[11];
    const float* bn2_b    = (const float*)d_in[12];
    const float* bn2_m    = (const float*)d_in[13];
    const float* bn2_v    = (const float*)d_in[14];
    const float* id_w     = (const float*)d_in[15];
    const float* id_b     = (const float*)d_in[16];
    const float* bn3_g    = (const float*)d_in[17];
    const float* bn3_b    = (const float*)d_in[18];
    const float* bn3_m    = (const float*)d_in[19];
    const float* bn3_v    = (const float*)d_in[20];
    float* out = (float*)d_out;

    auto k1 = fused_gemm_kernel<CIN, K1, 36, 2, 36, 0, CIN / 16>;
    auto k2 = fused_gemm_kernel<COUT, K2, 76, 3, 72, 1, COUT / 16>;
    cudaFuncSetAttribute(k1, cudaFuncAttributeMaxDynamicSharedMemorySize, FGEMM_SMEM);
    cudaFuncSetAttribute(k2, cudaFuncAttributeMaxDynamicSharedMemorySize, FGEMM_SMEM);

    // launch #1: prep
    {
        int total = COUT * K1 + COUT * K2C + COUT * CIN;
        prep_all<<<(total + 255) / 256, 256>>>(dc1_w, dc2_w, id_w, id_b,
                                               bn1_g, bn1_b, bn1_m, bn1_v,
                                               bn2_g, bn2_b, bn2_m, bn2_v,
                                               bn3_g, bn3_b, bn3_m, bn3_v);
    }

    // layer 1
    offset_partial_kernel<<<dim3(WW / 16, HH / 16, BATCH * (CIN / 16)), 128>>>(
        x, 0, dc1_offw, CIN);
    k1<<<dim3(HWSZ / 128, BATCH), 256, FGEMM_SMEM>>>(x, dc1_offb, out);

    // layer 2
    offset_partial_kernel<<<dim3(WW / 16, HH / 16, BATCH * (COUT / 16)), 128>>>(
        x, 1, dc2_offw, COUT);
    k2<<<dim3(HWSZ / 128, BATCH), 256, FGEMM_SMEM>>>(x, dc2_offb, out);
}

// round 16
// speedup vs baseline: 1.3779x; 1.0632x over previous
#include <cuda_runtime.h>
#include <cuda_bf16.h>
#include <math.h>

#define BATCH 2
#define CIN   64
#define COUT  128
#define HH    128
#define WW    128
#define HWSZ  (HH*WW)          // 16384
#define K1    576              // 9*64
#define K2C   1152             // 9*128
#define K2    1216             // + 64 identity rows

// ---------------- scratch (static device globals) ----------------------------
__device__ float g_offp[8 * BATCH * 18 * HWSZ];             // per-chunk partials
__device__ float g_h1 [BATCH * COUT * HWSZ];
__device__ __nv_bfloat16 g_w1h[COUT * K1], g_w1l[COUT * K1];
__device__ __nv_bfloat16 g_w2h[COUT * K2], g_w2l[COUT * K2];
__device__ float g_b1[COUT], g_b2[COUT];

// ---------------- PTX helpers (sm_80-era only; compute_103-safe) -------------
__device__ __forceinline__ unsigned smem_u32(const void* p) {
    unsigned a;
    asm("{ .reg .u64 t; cvta.to.shared.u64 t, %1; cvt.u32.u64 %0, t; }"
        : "=r"(a) : "l"(p));
    return a;
}
__device__ __forceinline__ void cp16(unsigned dst, const void* src) {
    asm volatile("cp.async.cg.shared.global [%0], [%1], 16;"
                 :: "r"(dst), "l"(src) : "memory");
}
__device__ __forceinline__ void cp_commit() {
    asm volatile("cp.async.commit_group;" ::: "memory");
}
__device__ __forceinline__ void cp_wait0() {
    asm volatile("cp.async.wait_group 0;" ::: "memory");
}
__device__ __forceinline__ void ldm_x4(unsigned a, unsigned r[4]) {
    asm volatile("ldmatrix.sync.aligned.m8n8.x4.shared.b16 {%0,%1,%2,%3}, [%4];"
                 : "=r"(r[0]), "=r"(r[1]), "=r"(r[2]), "=r"(r[3]) : "r"(a));
}
__device__ __forceinline__ void mma16816(float d[4], const unsigned a[4],
                                         unsigned b0, unsigned b1) {
    asm volatile(
        "mma.sync.aligned.m16n8k16.row.col.f32.bf16.bf16.f32 "
        "{%0,%1,%2,%3}, {%4,%5,%6,%7}, {%8,%9}, {%0,%1,%2,%3};"
        : "+f"(d[0]), "+f"(d[1]), "+f"(d[2]), "+f"(d[3])
        : "r"(a[0]), "r"(a[1]), "r"(a[2]), "r"(a[3]), "r"(b0), "r"(b1));
}
__device__ __forceinline__ unsigned pack_bf2(float a, float b) {
    return (unsigned)__bfloat16_as_ushort(__float2bfloat16(a)) |
           ((unsigned)__bfloat16_as_ushort(__float2bfloat16(b)) << 16);
}
__device__ __forceinline__ float lo_of(float v) {
    return v - __bfloat162float(__float2bfloat16(v));
}

// ---------------- merged weight/bias prep ------------------------------------
__device__ __forceinline__ float bn_scale(const float* g, const float* v, int o) {
    return g[o] * rsqrtf(v[o] + 1e-5f);
}
__device__ __forceinline__ void split_store(__nv_bfloat16* hd, __nv_bfloat16* ld,
                                            long i, float v) {
    __nv_bfloat16 h = __float2bfloat16(v);
    hd[i] = h;
    ld[i] = __float2bfloat16(v - __bfloat162float(h));
}

__global__ void prep_all(const float* __restrict__ dc1_w,
                         const float* __restrict__ dc2_w,
                         const float* __restrict__ id_w,
                         const float* __restrict__ id_b,
                         const float* __restrict__ bn1_g, const float* __restrict__ bn1_b,
                         const float* __restrict__ bn1_m, const float* __restrict__ bn1_v,
                         const float* __restrict__ bn2_g, const float* __restrict__ bn2_b,
                         const float* __restrict__ bn2_m, const float* __restrict__ bn2_v,
                         const float* __restrict__ bn3_g, const float* __restrict__ bn3_b,
                         const float* __restrict__ bn3_m, const float* __restrict__ bn3_v)
{
    int idx = blockIdx.x * blockDim.x + threadIdx.x;
    if (idx < COUT) {
        int o = idx;
        float s1 = bn_scale(bn1_g, bn1_v, o);
        float s2 = bn_scale(bn2_g, bn2_v, o);
        float s3 = bn_scale(bn3_g, bn3_v, o);
        g_b1[o] = bn1_b[o] - bn1_m[o] * s1;
        g_b2[o] = (bn2_b[o] - bn2_m[o] * s2) + id_b[o] * s3 + (bn3_b[o] - bn3_m[o] * s3);
    }
    const int n1 = COUT * K1, n2 = COUT * K2C, n3 = COUT * CIN;
    if (idx < n1) {
        int o = idx / K1, kk = idx % K1;
        int c = kk / 9, n = kk % 9;
        float v = dc1_w[idx] * bn_scale(bn1_g, bn1_v, o);
        split_store(g_w1h, g_w1l, (long)o * K1 + n * CIN + c, v);
    } else if (idx < n1 + n2) {
        int r = idx - n1;
        int o = r / K2C, kk = r % K2C;
        int c = kk / 9, n = kk % 9;
        float v = dc2_w[r] * bn_scale(bn2_g, bn2_v, o);
        split_store(g_w2h, g_w2l, (long)o * K2 + n * COUT + c, v);
    } else if (idx < n1 + n2 + n3) {
        int r = idx - n1 - n2;
        int o = r / CIN, c = r % CIN;
        float v = id_w[r] * bn_scale(bn3_g, bn3_v, o);
        split_store(g_w2h, g_w2l, (long)o * K2 + K2C + c, v);
    }
}

// ---------------- offset conv: smem-tiled partial conv (vectorized LDS) ------
// ws row stride padded to 20 floats (80 B, 16B-aligned) -> 4xLDS.128 + LDS.64
#define WSTR 20
__global__ __launch_bounds__(128)
void offset_partial_kernel(const float* __restrict__ xext, int use_h1,
                           const float* __restrict__ ow, int C)
{
    __shared__ __align__(16) float xs[16][324];
    __shared__ __align__(16) float ws[16 * 9 * WSTR];
    const float* x = use_h1 ? g_h1 : xext;
    const int CH = C / 16;
    const int z = blockIdx.z;
    const int b = z / CH, ch = z % CH, c0 = ch * 16;
    const int tx0 = blockIdx.x * 16, ty0 = blockIdx.y * 16;
    const int t = threadIdx.x;
    const int py = t >> 4, px = t & 15;

    for (int i = t; i < 16 * 9 * 18; i += 128) {
        int ct = i / 18, o = i % 18;          // ct = c*9+tap
        int c = ct / 9, tap = ct % 9;
        ws[ct * WSTR + o] = ow[o * C * 9 + (c0 + c) * 9 + tap];
    }
    for (int i = t; i < 16 * 324; i += 128) {
        int c = i / 324, rr = (i % 324) / 18, cc = i % 18;
        int gy = ty0 - 1 + rr, gx = tx0 - 1 + cc;
        float v = 0.f;
        if ((unsigned)gy < (unsigned)HH && (unsigned)gx < (unsigned)WW)
            v = x[((long)b * C + c0 + c) * HWSZ + gy * WW + gx];
        xs[c][rr * 18 + cc] = v;
    }
    __syncthreads();

    float acc[2][18];
#pragma unroll
    for (int q = 0; q < 2; ++q)
#pragma unroll
        for (int o = 0; o < 18; ++o) acc[q][o] = 0.f;

    for (int c = 0; c < 16; ++c) {
#pragma unroll
        for (int tap = 0; tap < 9; ++tap) {
            int ky = tap / 3, kx = tap % 3;
            float xv0 = xs[c][(py + ky) * 18 + px + kx];
            float xv1 = xs[c][(py + 8 + ky) * 18 + px + kx];
            const float* wrow = &ws[(c * 9 + tap) * WSTR];
            float4 w0 = *(const float4*)(wrow + 0);
            float4 w1 = *(const float4*)(wrow + 4);
            float4 w2 = *(const float4*)(wrow + 8);
            float4 w3 = *(const float4*)(wrow + 12);
            float2 w4 = *(const float2*)(wrow + 16);
            float wv[18] = {w0.x, w0.y, w0.z, w0.w, w1.x, w1.y, w1.z, w1.w,
                            w2.x, w2.y, w2.z, w2.w, w3.x, w3.y, w3.z, w3.w,
                            w4.x, w4.y};
#pragma unroll
            for (int o = 0; o < 18; ++o) {
                acc[0][o] += wv[o] * xv0;
                acc[1][o] += wv[o] * xv1;
            }
        }
    }

    float* pp = g_offp + (long)ch * (BATCH * 18 * HWSZ);
#pragma unroll
    for (int q = 0; q < 2; ++q) {
        int row = ty0 + py + q * 8;
#pragma unroll
        for (int o = 0; o < 18; ++o)
            pp[((long)b * 18 + o) * HWSZ + row * WW + tx0 + px] = acc[q][o];
    }
}

// ---------------- fused sample + HMMA bf16x3 GEMM, N=128 tiles ---------------
#define ROWB2 48
#define A_MAT (128 * ROWB2)           // 6144
#define A_BUF (2 * A_MAT)             // 12288 (hi+lo)
#define B_MAT (128 * ROWB2)           // 6144
#define B_BUF (2 * B_MAT)             // 12288
#define SM_W4 0
#define SM_J4 18432
#define SM_A  36864
#define SM_B  (SM_A + 2 * A_BUF)      // 61440
#define FGEMM_SMEM (SM_B + 2 * B_BUF) // 86016

template<int C, int KTOT, int NCH, int CSH, int IDST, int SEL, int CHP>
__global__ __launch_bounds__(256, 2)
void fused_gemm_kernel(const float* __restrict__ xptr,
                       const float* __restrict__ offb,
                       float* __restrict__ dout)
{
    extern __shared__ char sm[];
    float4* sw4 = (float4*)(sm + SM_W4);
    int4*   sj4 = (int4*)(sm + SM_J4);

    const __nv_bfloat16* Ah = SEL ? g_w2h : g_w1h;
    const __nv_bfloat16* Al = SEL ? g_w2l : g_w1l;
    const float* bias       = SEL ? g_b2  : g_b1;
    float* Cp               = SEL ? dout  : g_h1;
    const float* src        = SEL ? g_h1  : xptr;

    const int tid = threadIdx.x;
    const int warp = tid >> 5, lane = tid & 31;
    const int mbase = (warp >> 1) * 32;
    const int nbase = (warp & 1) * 64;
    const int b = blockIdx.y, j0 = blockIdx.x * 128;
    const unsigned sb = smem_u32(sm);

    // ---- precomp: fold offset reduce + bias, bilinear weights/indices -------
    for (int i = tid; i < 1152; i += 256) {
        int n = i >> 7, pxl = i & 127;
        int pix = j0 + pxl;
        int hh = pix >> 7, ww = pix & 127;
        const int planes = BATCH * 18 * HWSZ;
        float offy = offb[n], offx = offb[9 + n];
        long ybase = (long)(b * 18 + n) * HWSZ + pix;
        long xbase = (long)(b * 18 + 9 + n) * HWSZ + pix;
#pragma unroll
        for (int c = 0; c < CHP; ++c) {
            offy += g_offp[(long)c * planes + ybase];
            offx += g_offp[(long)c * planes + xbase];
        }
        float py = offy + (float)(n / 3 - 1) + (float)(hh + 1);
        float px = offx + (float)(n % 3 - 1) + (float)(ww + 1);
        const float hiB = 129.f;
        py = fminf(fmaxf(py, 0.f), hiB);
        px = fminf(fmaxf(px, 0.f), hiB);
        float fy = floorf(py), fx = floorf(px);
        float qy1 = fminf(fy + 1.f, hiB), qx1 = fminf(fx + 1.f, hiB);
        float dy0 = 1.f + (fy - py), dy1 = 1.f - (qy1 - py);
        float dx0 = 1.f + (fx - px), dx1 = 1.f - (qx1 - px);
        int iy0 = (int)fy - 1, ix0 = (int)fx - 1;
        int iy1 = (int)qy1 - 1, ix1 = (int)qx1 - 1;
        bool vy0 = (unsigned)iy0 < (unsigned)HH, vy1 = (unsigned)iy1 < (unsigned)HH;
        bool vx0 = (unsigned)ix0 < (unsigned)WW, vx1 = (unsigned)ix1 < (unsigned)WW;
        float w00 = (vy0 && vx0) ? dy0 * dx0 : 0.f;
        float w01 = (vy0 && vx1) ? dy0 * dx1 : 0.f;
        float w10 = (vy1 && vx0) ? dy1 * dx0 : 0.f;
        float w11 = (vy1 && vx1) ? dy1 * dx1 : 0.f;
        int cy0 = min(max(iy0, 0), HH - 1), cy1 = min(max(iy1, 0), HH - 1);
        int cx0 = min(max(ix0, 0), WW - 1), cx1 = min(max(ix1, 0), WW - 1);
        sw4[i] = make_float4(w00, w01, w10, w11);
        sj4[i] = make_int4(cy0 * WW + cx0, cy0 * WW + cx1,
                           cy1 * WW + cx0, cy1 * WW + cx1);
    }

    float d[2][8][4];
#pragma unroll
    for (int mt = 0; mt < 2; ++mt)
#pragma unroll
        for (int nt = 0; nt < 8; ++nt)
#pragma unroll
            for (int q = 0; q < 4; ++q) d[mt][nt][q] = 0.f;

    // gather mapping: 32 consecutive pixels per warp; 8 channels per thread
    const int cgrp = tid >> 7;          // 0..1, 8 channels each
    const int pxl  = tid & 127;
    const int pix  = j0 + pxl;
    const float* srcb = src + (long)b * C * HWSZ;
    const float* xb   = xptr + (long)b * CIN * HWSZ;

    float v[8];
    auto gather = [&](int ch) {
        if (ch < IDST) {
            int n = ch >> CSH, c0 = (ch & ((1 << CSH) - 1)) * 16 + cgrp * 8;
            int pi = (n << 7) | pxl;
            float4 wv = sw4[pi];
            int4 jv = sj4[pi];
#pragma unroll
            for (int u = 0; u < 8; ++u) {
                const float* pc = srcb + (long)(c0 + u) * HWSZ;
                v[u] = wv.x * pc[jv.x] + wv.y * pc[jv.y]
                     + wv.z * pc[jv.z] + wv.w * pc[jv.w];
            }
        } else {
            int c0 = (ch - IDST) * 16 + cgrp * 8;
#pragma unroll
            for (int u = 0; u < 8; ++u)
                v[u] = xb[(long)(c0 + u) * HWSZ + pix];
        }
    };
    auto storeB = [&](unsigned p) {
        char* base = sm + SM_B + p * B_BUF + pxl * ROWB2 + cgrp * 16;
#pragma unroll
        for (int g = 0; g < 2; ++g) {
            unsigned h0 = pack_bf2(v[g * 4 + 0], v[g * 4 + 1]);
            unsigned h1 = pack_bf2(v[g * 4 + 2], v[g * 4 + 3]);
            unsigned l0 = pack_bf2(lo_of(v[g * 4 + 0]), lo_of(v[g * 4 + 1]));
            unsigned l1 = pack_bf2(lo_of(v[g * 4 + 2]), lo_of(v[g * 4 + 3]));
            *(uint2*)(base + g * 8)         = make_uint2(h0, h1);
            *(uint2*)(base + B_MAT + g * 8) = make_uint2(l0, l1);
        }
    };
    auto loadA = [&](int ch, unsigned p) {
        int k0 = ch * 16;
        int r = tid >> 1, seg = tid & 1;
        unsigned dst = sb + SM_A + p * A_BUF + r * ROWB2 + seg * 16;
        cp16(dst,         Ah + (long)r * KTOT + k0 + seg * 8);
        cp16(dst + A_MAT, Al + (long)r * KTOT + k0 + seg * 8);
        cp_commit();
    };

    const unsigned a_off = (unsigned)(mbase + (lane & 15)) * ROWB2 +
                           (unsigned)((lane >> 4) & 1) * 16u;
    const unsigned b_off = (unsigned)(nbase + (lane & 7) + (((lane >> 4) & 1) << 3)) * ROWB2 +
                           (unsigned)((lane >> 3) & 1) * 16u;

    __syncthreads();          // precomp visible
    gather(0);
    storeB(0);
    loadA(0, 0);

    unsigned p = 0;
    for (int ch = 0; ch < NCH; ++ch) {
        cp_wait0();
        __syncthreads();
        if (ch + 1 < NCH) {
            gather(ch + 1);
            loadA(ch + 1, p ^ 1);
        }
        {
            unsigned abase = sb + SM_A + p * A_BUF;
            unsigned bbase = sb + SM_B + p * B_BUF;
            unsigned ah[2][4], al[2][4], bh[4][4], bl[4][4];
#pragma unroll
            for (int mt = 0; mt < 2; ++mt) {
                unsigned addr = abase + a_off + mt * 16u * ROWB2;
                ldm_x4(addr, ah[mt]);
                ldm_x4(addr + A_MAT, al[mt]);
            }
#pragma unroll
            for (int np = 0; np < 4; ++np) {
                unsigned addr = bbase + b_off + np * 16u * ROWB2;
                ldm_x4(addr, bh[np]);
                ldm_x4(addr + B_MAT, bl[np]);
            }
#pragma unroll
            for (int mt = 0; mt < 2; ++mt) {
#pragma unroll
                for (int nt = 0; nt < 8; ++nt) {
                    int np = nt >> 1, rp = (nt & 1) * 2;
                    mma16816(d[mt][nt], ah[mt], bh[np][rp], bh[np][rp + 1]);
                    mma16816(d[mt][nt], ah[mt], bl[np][rp], bl[np][rp + 1]);
                    mma16816(d[mt][nt], al[mt], bh[np][rp], bh[np][rp + 1]);
                }
            }
        }
        if (ch + 1 < NCH) storeB(p ^ 1);
        p ^= 1;
    }

    // epilogue: bias + relu
    const int qr = lane >> 2;
    const int qc = (lane & 3) * 2;
#pragma unroll
    for (int mt = 0; mt < 2; ++mt) {
        int o0 = mbase + mt * 16 + qr;
        int o1 = o0 + 8;
        float bs0 = bias[o0], bs1 = bias[o1];
        float* row0 = Cp + ((long)b * COUT + o0) * HWSZ + j0 + nbase + qc;
        float* row1 = Cp + ((long)b * COUT + o1) * HWSZ + j0 + nbase + qc;
#pragma unroll
        for (int nt = 0; nt < 8; ++nt) {
            float* acc = d[mt][nt];
            *(float2*)(row0 + nt * 8) =
                make_float2(fmaxf(acc[0] + bs0, 0.f), fmaxf(acc[1] + bs0, 0.f));
            *(float2*)(row1 + nt * 8) =
                make_float2(fmaxf(acc[2] + bs1, 0.f), fmaxf(acc[3] + bs1, 0.f));
        }
    }
}

// ---------------- launch -----------------------------------------------------
extern "C" void kernel_launch(void* const* d_in, const int* in_sizes, int n_in,
                              void* d_out, int out_size)
{
    const float* x        = (const float*)d_in[0];
    const float* dc1_offw = (const float*)d_in[1];
    const float* dc1_offb = (const float*)d_in[2];
    const float* dc1_w    = (const float*)d_in[3];
    const float* bn1_g    = (const float*)d_in[4];
    const float* bn1_b    = (const float*)d_in[5];
    const float* bn1_m    = (const float*)d_in[6];
    const float* bn1_v    = (const float*)d_in[7];
    const float* dc2_offw = (const float*)d_in[8];
    const float* dc2_offb = (const float*)d_in[9];
    const float* dc2_w    = (const float*)d_in[10];
    const float* bn2_g    = (const float*)d_in[11];
    const float* bn2_b    = (const float*)d_in[12];
    const float* bn2_m    = (const float*)d_in[13];
    const float* bn2_v    = (const float*)d_in[14];
    const float* id_w     = (const float*)d_in[15];
    const float* id_b     = (const float*)d_in[16];
    const float* bn3_g    = (const float*)d_in[17];
    const float* bn3_b    = (const float*)d_in[18];
    const float* bn3_m    = (const float*)d_in[19];
    const float* bn3_v    = (const float*)d_in[20];
    float* out = (float*)d_out;

    auto k1 = fused_gemm_kernel<CIN, K1, 36, 2, 36, 0, CIN / 16>;
    auto k2 = fused_gemm_kernel<COUT, K2, 76, 3, 72, 1, COUT / 16>;
    cudaFuncSetAttribute(k1, cudaFuncAttributeMaxDynamicSharedMemorySize, FGEMM_SMEM);
    cudaFuncSetAttribute(k2, cudaFuncAttributeMaxDynamicSharedMemorySize, FGEMM_SMEM);

    // launch #1: prep
    {
        int total = COUT * K1 + COUT * K2C + COUT * CIN;
        prep_all<<<(total + 255) / 256, 256>>>(dc1_w, dc2_w, id_w, id_b,
                                               bn1_g, bn1_b, bn1_m, bn1_v,
                                               bn2_g, bn2_b, bn2_m, bn2_v,
                                               bn3_g, bn3_b, bn3_m, bn3_v);
    }

    // layer 1
    offset_partial_kernel<<<dim3(WW / 16, HH / 16, BATCH * (CIN / 16)), 128>>>(
        x, 0, dc1_offw, CIN);
    k1<<<dim3(HWSZ / 128, BATCH), 256, FGEMM_SMEM>>>(x, dc1_offb, out);

    // layer 2
    offset_partial_kernel<<<dim3(WW / 16, HH / 16, BATCH * (COUT / 16)), 128>>>(
        x, 1, dc2_offw, COUT);
    k2<<<dim3(HWSZ / 128, BATCH), 256, FGEMM_SMEM>>>(x, dc2_offb, out);
}

// round 17
// speedup vs baseline: 1.4207x; 1.0311x over previous
#include <cuda_runtime.h>
#include <cuda_bf16.h>
#include <math.h>

#define BATCH 2
#define CIN   64
#define COUT  128
#define HH    128
#define WW    128
#define HWSZ  (HH*WW)          // 16384
#define K1    576              // 9*64
#define K2C   1152             // 9*128
#define K2    1216             // + 64 identity rows

// ---------------- scratch (static device globals) ----------------------------
__device__ float g_offp[8 * BATCH * 18 * HWSZ];             // per-chunk partials
__device__ float g_h1 [BATCH * COUT * HWSZ];
__device__ __nv_bfloat16 g_w1h[COUT * K1], g_w1l[COUT * K1];
__device__ __nv_bfloat16 g_w2h[COUT * K2], g_w2l[COUT * K2];
__device__ float g_b1[COUT], g_b2[COUT];

// ---------------- PTX helpers (sm_80-era + sm_100 base f32x2) ----------------
__device__ __forceinline__ unsigned smem_u32(const void* p) {
    unsigned a;
    asm("{ .reg .u64 t; cvta.to.shared.u64 t, %1; cvt.u32.u64 %0, t; }"
        : "=r"(a) : "l"(p));
    return a;
}
__device__ __forceinline__ void cp16(unsigned dst, const void* src) {
    asm volatile("cp.async.cg.shared.global [%0], [%1], 16;"
                 :: "r"(dst), "l"(src) : "memory");
}
__device__ __forceinline__ void cp_commit() {
    asm volatile("cp.async.commit_group;" ::: "memory");
}
__device__ __forceinline__ void cp_wait0() {
    asm volatile("cp.async.wait_group 0;" ::: "memory");
}
__device__ __forceinline__ void ldm_x4(unsigned a, unsigned r[4]) {
    asm volatile("ldmatrix.sync.aligned.m8n8.x4.shared.b16 {%0,%1,%2,%3}, [%4];"
                 : "=r"(r[0]), "=r"(r[1]), "=r"(r[2]), "=r"(r[3]) : "r"(a));
}
__device__ __forceinline__ void mma16816(float d[4], const unsigned a[4],
                                         unsigned b0, unsigned b1) {
    asm volatile(
        "mma.sync.aligned.m16n8k16.row.col.f32.bf16.bf16.f32 "
        "{%0,%1,%2,%3}, {%4,%5,%6,%7}, {%8,%9}, {%0,%1,%2,%3};"
        : "+f"(d[0]), "+f"(d[1]), "+f"(d[2]), "+f"(d[3])
        : "r"(a[0]), "r"(a[1]), "r"(a[2]), "r"(a[3]), "r"(b0), "r"(b1));
}
__device__ __forceinline__ unsigned pack_bf2(float a, float b) {
    return (unsigned)__bfloat16_as_ushort(__float2bfloat16(a)) |
           ((unsigned)__bfloat16_as_ushort(__float2bfloat16(b)) << 16);
}
__device__ __forceinline__ float lo_of(float v) {
    return v - __bfloat162float(__float2bfloat16(v));
}
// packed f32x2 (sm_100+ base ISA)
__device__ __forceinline__ unsigned long long ffma2(unsigned long long a,
                                                    unsigned long long b,
                                                    unsigned long long c) {
    unsigned long long d;
    asm("fma.rn.f32x2 %0, %1, %2, %3;" : "=l"(d) : "l"(a), "l"(b), "l"(c));
    return d;
}
__device__ __forceinline__ unsigned long long bcast2(float x) {
    unsigned long long d;
    asm("mov.b64 %0, {%1, %1};" : "=l"(d) : "f"(x));
    return d;
}
__device__ __forceinline__ void unpack2(unsigned long long v, float& lo, float& hi) {
    asm("mov.b64 {%0, %1}, %2;" : "=f"(lo), "=f"(hi) : "l"(v));
}

// ---------------- merged weight/bias prep ------------------------------------
__device__ __forceinline__ float bn_scale(const float* g, const float* v, int o) {
    return g[o] * rsqrtf(v[o] + 1e-5f);
}
__device__ __forceinline__ void split_store(__nv_bfloat16* hd, __nv_bfloat16* ld,
                                            long i, float v) {
    __nv_bfloat16 h = __float2bfloat16(v);
    hd[i] = h;
    ld[i] = __float2bfloat16(v - __bfloat162float(h));
}

__global__ void prep_all(const float* __restrict__ dc1_w,
                         const float* __restrict__ dc2_w,
                         const float* __restrict__ id_w,
                         const float* __restrict__ id_b,
                         const float* __restrict__ bn1_g, const float* __restrict__ bn1_b,
                         const float* __restrict__ bn1_m, const float* __restrict__ bn1_v,
                         const float* __restrict__ bn2_g, const float* __restrict__ bn2_b,
                         const float* __restrict__ bn2_m, const float* __restrict__ bn2_v,
                         const float* __restrict__ bn3_g, const float* __restrict__ bn3_b,
                         const float* __restrict__ bn3_m, const float* __restrict__ bn3_v)
{
    int idx = blockIdx.x * blockDim.x + threadIdx.x;
    if (idx < COUT) {
        int o = idx;
        float s1 = bn_scale(bn1_g, bn1_v, o);
        float s2 = bn_scale(bn2_g, bn2_v, o);
        float s3 = bn_scale(bn3_g, bn3_v, o);
        g_b1[o] = bn1_b[o] - bn1_m[o] * s1;
        g_b2[o] = (bn2_b[o] - bn2_m[o] * s2) + id_b[o] * s3 + (bn3_b[o] - bn3_m[o] * s3);
    }
    const int n1 = COUT * K1, n2 = COUT * K2C, n3 = COUT * CIN;
    if (idx < n1) {
        int o = idx / K1, kk = idx % K1;
        int c = kk / 9, n = kk % 9;
        float v = dc1_w[idx] * bn_scale(bn1_g, bn1_v, o);
        split_store(g_w1h, g_w1l, (long)o * K1 + n * CIN + c, v);
    } else if (idx < n1 + n2) {
        int r = idx - n1;
        int o = r / K2C, kk = r % K2C;
        int c = kk / 9, n = kk % 9;
        float v = dc2_w[r] * bn_scale(bn2_g, bn2_v, o);
        split_store(g_w2h, g_w2l, (long)o * K2 + n * COUT + c, v);
    } else if (idx < n1 + n2 + n3) {
        int r = idx - n1 - n2;
        int o = r / CIN, c = r % CIN;
        float v = id_w[r] * bn_scale(bn3_g, bn3_v, o);
        split_store(g_w2h, g_w2l, (long)o * K2 + K2C + c, v);
    }
}

// ---------------- offset conv: smem-tiled partial conv (FFMA2) ---------------
// ws row stride 20 floats (80 B, 16B-aligned); weight pairs consumed directly
// as f32x2 operands; 36 FMA per (c,tap) -> 18 FFMA2.
#define WSTR 20
__global__ __launch_bounds__(128)
void offset_partial_kernel(const float* __restrict__ xext, int use_h1,
                           const float* __restrict__ ow, int C)
{
    __shared__ __align__(16) float xs[16][324];
    __shared__ __align__(16) float ws[16 * 9 * WSTR];
    const float* x = use_h1 ? g_h1 : xext;
    const int CH = C / 16;
    const int z = blockIdx.z;
    const int b = z / CH, ch = z % CH, c0 = ch * 16;
    const int tx0 = blockIdx.x * 16, ty0 = blockIdx.y * 16;
    const int t = threadIdx.x;
    const int py = t >> 4, px = t & 15;

    for (int i = t; i < 16 * 9 * 18; i += 128) {
        int ct = i / 18, o = i % 18;          // ct = c*9+tap
        int c = ct / 9, tap = ct % 9;
        ws[ct * WSTR + o] = ow[o * C * 9 + (c0 + c) * 9 + tap];
    }
    for (int i = t; i < 16 * 324; i += 128) {
        int c = i / 324, rr = (i % 324) / 18, cc = i % 18;
        int gy = ty0 - 1 + rr, gx = tx0 - 1 + cc;
        float v = 0.f;
        if ((unsigned)gy < (unsigned)HH && (unsigned)gx < (unsigned)WW)
            v = x[((long)b * C + c0 + c) * HWSZ + gy * WW + gx];
        xs[c][rr * 18 + cc] = v;
    }
    __syncthreads();

    unsigned long long acc2[2][9];
#pragma unroll
    for (int q = 0; q < 2; ++q)
#pragma unroll
        for (int o = 0; o < 9; ++o) acc2[q][o] = 0ull;

    for (int c = 0; c < 16; ++c) {
#pragma unroll
        for (int tap = 0; tap < 9; ++tap) {
            int ky = tap / 3, kx = tap % 3;
            unsigned long long b0 = bcast2(xs[c][(py + ky) * 18 + px + kx]);
            unsigned long long b1 = bcast2(xs[c][(py + 8 + ky) * 18 + px + kx]);
            const float* wrow = &ws[(c * 9 + tap) * WSTR];
            const ulonglong2* wp = (const ulonglong2*)wrow;
            ulonglong2 wq0 = wp[0], wq1 = wp[1], wq2 = wp[2], wq3 = wp[3];
            unsigned long long w8 = *(const unsigned long long*)(wrow + 16);
            unsigned long long wv2[9] = {wq0.x, wq0.y, wq1.x, wq1.y,
                                         wq2.x, wq2.y, wq3.x, wq3.y, w8};
#pragma unroll
            for (int o = 0; o < 9; ++o) {
                acc2[0][o] = ffma2(wv2[o], b0, acc2[0][o]);
                acc2[1][o] = ffma2(wv2[o], b1, acc2[1][o]);
            }
        }
    }

    float* pp = g_offp + (long)ch * (BATCH * 18 * HWSZ);
#pragma unroll
    for (int q = 0; q < 2; ++q) {
        int row = ty0 + py + q * 8;
#pragma unroll
        for (int o = 0; o < 9; ++o) {
            float lo, hi;
            unpack2(acc2[q][o], lo, hi);
            pp[((long)b * 18 + 2 * o)     * HWSZ + row * WW + tx0 + px] = lo;
            pp[((long)b * 18 + 2 * o + 1) * HWSZ + row * WW + tx0 + px] = hi;
        }
    }
}

// ---------------- fused sample + HMMA bf16x3 GEMM, N=128 tiles ---------------
#define ROWB2 48
#define A_MAT (128 * ROWB2)           // 6144
#define A_BUF (2 * A_MAT)             // 12288 (hi+lo)
#define B_MAT (128 * ROWB2)           // 6144
#define B_BUF (2 * B_MAT)             // 12288
#define SM_W4 0
#define SM_J4 18432
#define SM_A  36864
#define SM_B  (SM_A + 2 * A_BUF)      // 61440
#define FGEMM_SMEM (SM_B + 2 * B_BUF) // 86016

template<int C, int KTOT, int NCH, int CSH, int IDST, int SEL, int CHP>
__global__ __launch_bounds__(256, 2)
void fused_gemm_kernel(const float* __restrict__ xptr,
                       const float* __restrict__ offb,
                       float* __restrict__ dout)
{
    extern __shared__ char sm[];
    float4* sw4 = (float4*)(sm + SM_W4);
    int4*   sj4 = (int4*)(sm + SM_J4);

    const __nv_bfloat16* Ah = SEL ? g_w2h : g_w1h;
    const __nv_bfloat16* Al = SEL ? g_w2l : g_w1l;
    const float* bias       = SEL ? g_b2  : g_b1;
    float* Cp               = SEL ? dout  : g_h1;
    const float* src        = SEL ? g_h1  : xptr;

    const int tid = threadIdx.x;
    const int warp = tid >> 5, lane = tid & 31;
    const int mbase = (warp >> 1) * 32;
    const int nbase = (warp & 1) * 64;
    const int b = blockIdx.y, j0 = blockIdx.x * 128;
    const unsigned sb = smem_u32(sm);

    // ---- precomp: fold offset reduce + bias, bilinear weights/indices -------
    for (int i = tid; i < 1152; i += 256) {
        int n = i >> 7, pxl = i & 127;
        int pix = j0 + pxl;
        int hh = pix >> 7, ww = pix & 127;
        const int planes = BATCH * 18 * HWSZ;
        float offy = offb[n], offx = offb[9 + n];
        long ybase = (long)(b * 18 + n) * HWSZ + pix;
        long xbase = (long)(b * 18 + 9 + n) * HWSZ + pix;
#pragma unroll
        for (int c = 0; c < CHP; ++c) {
            offy += g_offp[(long)c * planes + ybase];
            offx += g_offp[(long)c * planes + xbase];
        }
        float py = offy + (float)(n / 3 - 1) + (float)(hh + 1);
        float px = offx + (float)(n % 3 - 1) + (float)(ww + 1);
        const float hiB = 129.f;
        py = fminf(fmaxf(py, 0.f), hiB);
        px = fminf(fmaxf(px, 0.f), hiB);
        float fy = floorf(py), fx = floorf(px);
        float qy1 = fminf(fy + 1.f, hiB), qx1 = fminf(fx + 1.f, hiB);
        float dy0 = 1.f + (fy - py), dy1 = 1.f - (qy1 - py);
        float dx0 = 1.f + (fx - px), dx1 = 1.f - (qx1 - px);
        int iy0 = (int)fy - 1, ix0 = (int)fx - 1;
        int iy1 = (int)qy1 - 1, ix1 = (int)qx1 - 1;
        bool vy0 = (unsigned)iy0 < (unsigned)HH, vy1 = (unsigned)iy1 < (unsigned)HH;
        bool vx0 = (unsigned)ix0 < (unsigned)WW, vx1 = (unsigned)ix1 < (unsigned)WW;
        float w00 = (vy0 && vx0) ? dy0 * dx0 : 0.f;
        float w01 = (vy0 && vx1) ? dy0 * dx1 : 0.f;
        float w10 = (vy1 && vx0) ? dy1 * dx0 : 0.f;
        float w11 = (vy1 && vx1) ? dy1 * dx1 : 0.f;
        int cy0 = min(max(iy0, 0), HH - 1), cy1 = min(max(iy1, 0), HH - 1);
        int cx0 = min(max(ix0, 0), WW - 1), cx1 = min(max(ix1, 0), WW - 1);
        sw4[i] = make_float4(w00, w01, w10, w11);
        sj4[i] = make_int4(cy0 * WW + cx0, cy0 * WW + cx1,
                           cy1 * WW + cx0, cy1 * WW + cx1);
    }

    float d[2][8][4];
#pragma unroll
    for (int mt = 0; mt < 2; ++mt)
#pragma unroll
        for (int nt = 0; nt < 8; ++nt)
#pragma unroll
            for (int q = 0; q < 4; ++q) d[mt][nt][q] = 0.f;

    // gather mapping: 32 consecutive pixels per warp; 8 channels per thread
    const int cgrp = tid >> 7;          // 0..1, 8 channels each
    const int pxl  = tid & 127;
    const int pix  = j0 + pxl;
    const float* srcb = src + (long)b * C * HWSZ;
    const float* xb   = xptr + (long)b * CIN * HWSZ;

    float v[8];
    auto gather = [&](int ch) {
        if (ch < IDST) {
            int n = ch >> CSH, c0 = (ch & ((1 << CSH) - 1)) * 16 + cgrp * 8;
            int pi = (n << 7) | pxl;
            float4 wv = sw4[pi];
            int4 jv = sj4[pi];
#pragma unroll
            for (int u = 0; u < 8; ++u) {
                const float* pc = srcb + (long)(c0 + u) * HWSZ;
                v[u] = wv.x * pc[jv.x] + wv.y * pc[jv.y]
                     + wv.z * pc[jv.z] + wv.w * pc[jv.w];
            }
        } else {
            int c0 = (ch - IDST) * 16 + cgrp * 8;
#pragma unroll
            for (int u = 0; u < 8; ++u)
                v[u] = xb[(long)(c0 + u) * HWSZ + pix];
        }
    };
    auto storeB = [&](unsigned p) {
        char* base = sm + SM_B + p * B_BUF + pxl * ROWB2 + cgrp * 16;
#pragma unroll
        for (int g = 0; g < 2; ++g) {
            unsigned h0 = pack_bf2(v[g * 4 + 0], v[g * 4 + 1]);
            unsigned h1 = pack_bf2(v[g * 4 + 2], v[g * 4 + 3]);
            unsigned l0 = pack_bf2(lo_of(v[g * 4 + 0]), lo_of(v[g * 4 + 1]));
            unsigned l1 = pack_bf2(lo_of(v[g * 4 + 2]), lo_of(v[g * 4 + 3]));
            *(uint2*)(base + g * 8)         = make_uint2(h0, h1);
            *(uint2*)(base + B_MAT + g * 8) = make_uint2(l0, l1);
        }
    };
    auto loadA = [&](int ch, unsigned p) {
        int k0 = ch * 16;
        int r = tid >> 1, seg = tid & 1;
        unsigned dst = sb + SM_A + p * A_BUF + r * ROWB2 + seg * 16;
        cp16(dst,         Ah + (long)r * KTOT + k0 + seg * 8);
        cp16(dst + A_MAT, Al + (long)r * KTOT + k0 + seg * 8);
        cp_commit();
    };

    const unsigned a_off = (unsigned)(mbase + (lane & 15)) * ROWB2 +
                           (unsigned)((lane >> 4) & 1) * 16u;
    const unsigned b_off = (unsigned)(nbase + (lane & 7) + (((lane >> 4) & 1) << 3)) * ROWB2 +
                           (unsigned)((lane >> 3) & 1) * 16u;

    __syncthreads();          // precomp visible
    gather(0);
    storeB(0);
    loadA(0, 0);

    unsigned p = 0;
    for (int ch = 0; ch < NCH; ++ch) {
        cp_wait0();
        __syncthreads();
        if (ch + 1 < NCH) {
            gather(ch + 1);
            loadA(ch + 1, p ^ 1);
        }
        {
            unsigned abase = sb + SM_A + p * A_BUF;
            unsigned bbase = sb + SM_B + p * B_BUF;
            unsigned ah[2][4], al[2][4], bh[4][4], bl[4][4];
#pragma unroll
            for (int mt = 0; mt < 2; ++mt) {
                unsigned addr = abase + a_off + mt * 16u * ROWB2;
                ldm_x4(addr, ah[mt]);
                ldm_x4(addr + A_MAT, al[mt]);
            }
#pragma unroll
            for (int np = 0; np < 4; ++np) {
                unsigned addr = bbase + b_off + np * 16u * ROWB2;
                ldm_x4(addr, bh[np]);
                ldm_x4(addr + B_MAT, bl[np]);
            }
#pragma unroll
            for (int mt = 0; mt < 2; ++mt) {
#pragma unroll
                for (int nt = 0; nt < 8; ++nt) {
                    int np = nt >> 1, rp = (nt & 1) * 2;
                    mma16816(d[mt][nt], ah[mt], bh[np][rp], bh[np][rp + 1]);
                    mma16816(d[mt][nt], ah[mt], bl[np][rp], bl[np][rp + 1]);
                    mma16816(d[mt][nt], al[mt], bh[np][rp], bh[np][rp + 1]);
                }
            }
        }
        if (ch + 1 < NCH) storeB(p ^ 1);
        p ^= 1;
    }

    // epilogue: bias + relu
    const int qr = lane >> 2;
    const int qc = (lane & 3) * 2;
#pragma unroll
    for (int mt = 0; mt < 2; ++mt) {
        int o0 = mbase + mt * 16 + qr;
        int o1 = o0 + 8;
        float bs0 = bias[o0], bs1 = bias[o1];
        float* row0 = Cp + ((long)b * COUT + o0) * HWSZ + j0 + nbase + qc;
        float* row1 = Cp + ((long)b * COUT + o1) * HWSZ + j0 + nbase + qc;
#pragma unroll
        for (int nt = 0; nt < 8; ++nt) {
            float* acc = d[mt][nt];
            *(float2*)(row0 + nt * 8) =
                make_float2(fmaxf(acc[0] + bs0, 0.f), fmaxf(acc[1] + bs0, 0.f));
            *(float2*)(row1 + nt * 8) =
                make_float2(fmaxf(acc[2] + bs1, 0.f), fmaxf(acc[3] + bs1, 0.f));
        }
    }
}

// ---------------- launch -----------------------------------------------------
extern "C" void kernel_launch(void* const* d_in, const int* in_sizes, int n_in,
                              void* d_out, int out_size)
{
    const float* x        = (const float*)d_in[0];
    const float* dc1_offw = (const float*)d_in[1];
    const float* dc1_offb = (const float*)d_in[2];
    const float* dc1_w    = (const float*)d_in[3];
    const float* bn1_g    = (const float*)d_in[4];
    const float* bn1_b    = (const float*)d_in[5];
    const float* bn1_m    = (const float*)d_in[6];
    const float* bn1_v    = (const float*)d_in[7];
    const float* dc2_offw = (const float*)d_in[8];
    const float* dc2_offb = (const float*)d_in[9];
    const float* dc2_w    = (const float*)d_in[10];
    const float* bn2_g    = (const float*)d_in[11];
    const float* bn2_b    = (const float*)d_in[12];
    const float* bn2_m    = (const float*)d_in[13];
    const float* bn2_v    = (const float*)d_in[14];
    const float* id_w     = (const float*)d_in[15];
    const float* id_b     = (const float*)d_in[16];
    const float* bn3_g    = (const float*)d_in[17];
    const float* bn3_b    = (const float*)d_in[18];
    const float* bn3_m    = (const float*)d_in[19];
    const float* bn3_v    = (const float*)d_in[20];
    float* out = (float*)d_out;

    auto k1 = fused_gemm_kernel<CIN, K1, 36, 2, 36, 0, CIN / 16>;
    auto k2 = fused_gemm_kernel<COUT, K2, 76, 3, 72, 1, COUT / 16>;
    cudaFuncSetAttribute(k1, cudaFuncAttributeMaxDynamicSharedMemorySize, FGEMM_SMEM);
    cudaFuncSetAttribute(k2, cudaFuncAttributeMaxDynamicSharedMemorySize, FGEMM_SMEM);

    // launch #1: prep
    {
        int total = COUT * K1 + COUT * K2C + COUT * CIN;
        prep_all<<<(total + 255) / 256, 256>>>(dc1_w, dc2_w, id_w, id_b,
                                               bn1_g, bn1_b, bn1_m, bn1_v,
                                               bn2_g, bn2_b, bn2_m, bn2_v,
                                               bn3_g, bn3_b, bn3_m, bn3_v);
    }

    // layer 1
    offset_partial_kernel<<<dim3(WW / 16, HH / 16, BATCH * (CIN / 16)), 128>>>(
        x, 0, dc1_offw, CIN);
    k1<<<dim3(HWSZ / 128, BATCH), 256, FGEMM_SMEM>>>(x, dc1_offb, out);

    // layer 2
    offset_partial_kernel<<<dim3(WW / 16, HH / 16, BATCH * (COUT / 16)), 128>>>(
        x, 1, dc2_offw, COUT);
    k2<<<dim3(HWSZ / 128, BATCH), 256, FGEMM_SMEM>>>(x, dc2_offb, out);
}